// round 2
// baseline (speedup 1.0000x reference)
#include <cuda_runtime.h>
#include <math.h>

#define NB_   32
#define NC_   6
#define NIMG  384          // B*NB*NC = 2*32*6
#define NBOX  64           // B*NB
#define CROP_ 224
#define IMG_H_ 512
#define IMG_W_ 1408
#define DIM_  1024

// ---------------- scratch (device globals; no allocation) ----------------
__device__ float g_theta[NIMG * 6];
__device__ int   g_valid[NIMG];
__device__ float g_crops[NIMG * 3 * CROP_ * CROP_];        // 231 MB
__device__ float g_h1[NIMG * 64 * 56 * 56];                // 308 MB
__device__ float g_h2[NIMG * 256 * 14 * 14];               // 77 MB
__device__ float g_h3[NIMG * 1024 * 49];                   // 77 MB
__device__ float g_tok[NIMG * 50 * 1024];                  // 79 MB
__device__ float g_k[NIMG * 50 * 1024];                    // 79 MB
__device__ float g_v[NIMG * 50 * 1024];                    // 79 MB
__device__ float g_q[NIMG * 1024];
__device__ float g_emb[NIMG * 1024];

// ---------------- stage 0: projection + affine theta ----------------
__global__ void k_setup(const float* __restrict__ pred_boxes,
                        const float* __restrict__ la_m,
                        const float* __restrict__ l2i_m,
                        const float* __restrict__ aug_m,
                        const float* __restrict__ theta_w,
                        const float* __restrict__ theta_b) {
    int t = blockIdx.x * blockDim.x + threadIdx.x;
    if (t >= NIMG) return;
    int n = t / NC_, c = t % NC_;
    int b = n / NB_, nb = n % NB_;
    const float* pb = pred_boxes + (b * NB_ + nb) * 9;

    float r[4];
#pragma unroll
    for (int i = 0; i < 4; i++) {
        float s = theta_b[i];
#pragma unroll
        for (int j = 0; j < 9; j++) s += theta_w[i * 9 + j] * pb[j];
        r[i] = tanhf(s);
    }

    const float* la = la_m + b * 16;
    float px0 = pb[0] - la[3], py0 = pb[1] - la[7], pz0 = pb[2] - la[11];
    float a00 = la[0], a01 = la[1], a02 = la[2];
    float a10 = la[4], a11 = la[5], a12 = la[6];
    float a20 = la[8], a21 = la[9], a22 = la[10];
    float det = a00 * (a11 * a22 - a12 * a21) - a01 * (a10 * a22 - a12 * a20)
              + a02 * (a10 * a21 - a11 * a20);
    float id = 1.f / det;
    float i00 = (a11 * a22 - a12 * a21) * id, i01 = (a02 * a21 - a01 * a22) * id, i02 = (a01 * a12 - a02 * a11) * id;
    float i10 = (a12 * a20 - a10 * a22) * id, i11 = (a00 * a22 - a02 * a20) * id, i12 = (a02 * a10 - a00 * a12) * id;
    float i20 = (a10 * a21 - a11 * a20) * id, i21 = (a01 * a20 - a00 * a21) * id, i22 = (a00 * a11 - a01 * a10) * id;
    float px = i00 * px0 + i01 * py0 + i02 * pz0;
    float py = i10 * px0 + i11 * py0 + i12 * pz0;
    float pz = i20 * px0 + i21 * py0 + i22 * pz0;

    const float* m = l2i_m + (b * NC_ + c) * 16;
    float qx = m[0] * px + m[1] * py + m[2] * pz + m[3];
    float qy = m[4] * px + m[5] * py + m[6] * pz + m[7];
    float qz = m[8] * px + m[9] * py + m[10] * pz + m[11];
    float z = fminf(fmaxf(qz, 1e-5f), 100000.f);
    float x = qx / z, y = qy / z;
    const float* g = aug_m + (b * NC_ + c) * 16;
    float u = g[0] * x + g[1] * y + g[2] * z + g[3];
    float v = g[4] * x + g[5] * y + g[6] * z + g[7];
    int on = (v < (float)IMG_H_) && (v >= 0.f) && (u < (float)IMG_W_) && (u >= 0.f);
    float ty = v / (float)IMG_H_ * 2.f - 1.f;
    float tx = u / (float)IMG_W_ * 2.f - 1.f;

    int idx = n * NC_ + c;
    g_theta[idx * 6 + 0] = r[0]; g_theta[idx * 6 + 1] = r[1]; g_theta[idx * 6 + 2] = tx;
    g_theta[idx * 6 + 3] = r[2]; g_theta[idx * 6 + 4] = r[3]; g_theta[idx * 6 + 5] = ty;
    g_valid[idx] = on;
}

// ---------------- stage 1: bilinear grid sample -> crops ----------------
__global__ void k_sample(const float* __restrict__ imgs) {
    int img = blockIdx.y;
    int p = blockIdx.x * blockDim.x + threadIdx.x;
    if (p >= CROP_ * CROP_) return;
    int oy = p / CROP_, ox = p - oy * CROP_;
    const float* th = g_theta + img * 6;
    float gx = (2.f * ox + 1.f) / CROP_ - 1.f;
    float gy = (2.f * oy + 1.f) / CROP_ - 1.f;
    float grx = th[0] * gx + th[1] * gy + th[2];
    float gry = th[3] * gx + th[4] * gy + th[5];
    float ix = ((grx + 1.f) * IMG_W_ - 1.f) * 0.5f;
    float iy = ((gry + 1.f) * IMG_H_ - 1.f) * 0.5f;
    float x0 = floorf(ix), y0 = floorf(iy);
    float wx = ix - x0, wy = iy - y0;
    float x1 = x0 + 1.f, y1 = y0 + 1.f;

    int n = img / NC_, c = img - n * NC_, b = n / NB_;
    const float* base = imgs + (size_t)(b * NC_ + c) * 3 * IMG_H_ * IMG_W_;

    int xi0 = (int)fminf(fmaxf(x0, 0.f), (float)(IMG_W_ - 1));
    int xi1 = (int)fminf(fmaxf(x1, 0.f), (float)(IMG_W_ - 1));
    int yi0 = (int)fminf(fmaxf(y0, 0.f), (float)(IMG_H_ - 1));
    int yi1 = (int)fminf(fmaxf(y1, 0.f), (float)(IMG_H_ - 1));
    float vx0 = (x0 >= 0.f && x0 <= (float)(IMG_W_ - 1)) ? 1.f : 0.f;
    float vx1 = (x1 >= 0.f && x1 <= (float)(IMG_W_ - 1)) ? 1.f : 0.f;
    float vy0 = (y0 >= 0.f && y0 <= (float)(IMG_H_ - 1)) ? 1.f : 0.f;
    float vy1 = (y1 >= 0.f && y1 <= (float)(IMG_H_ - 1)) ? 1.f : 0.f;
    float w00 = (1.f - wx) * (1.f - wy) * vx0 * vy0;
    float w01 = wx * (1.f - wy) * vx1 * vy0;
    float w10 = (1.f - wx) * wy * vx0 * vy1;
    float w11 = wx * wy * vx1 * vy1;

#pragma unroll
    for (int ch = 0; ch < 3; ch++) {
        const float* ib = base + (size_t)ch * IMG_H_ * IMG_W_;
        float v00 = ib[yi0 * IMG_W_ + xi0];
        float v01 = ib[yi0 * IMG_W_ + xi1];
        float v10 = ib[yi1 * IMG_W_ + xi0];
        float v11 = ib[yi1 * IMG_W_ + xi1];
        g_crops[(((size_t)img * 3 + ch) * CROP_ + oy) * CROP_ + ox] =
            v00 * w00 + v01 * w01 + v10 * w10 + v11 * w11;
    }
}

// ---------------- GEMM tile helpers (64x64 C tile, K-chunks of 16) ----------------
#define GEMM_COMPUTE()                                                        \
    __syncthreads();                                                          \
    _Pragma("unroll")                                                         \
    for (int k = 0; k < 16; k++) {                                            \
        float a0 = As[k][ty4 + 0], a1 = As[k][ty4 + 1],                       \
              a2 = As[k][ty4 + 2], a3 = As[k][ty4 + 3];                       \
        float b0 = Bs[k][tx4 + 0], b1 = Bs[k][tx4 + 1],                       \
              b2 = Bs[k][tx4 + 2], b3 = Bs[k][tx4 + 3];                       \
        acc[0][0] = fmaf(a0, b0, acc[0][0]); acc[0][1] = fmaf(a0, b1, acc[0][1]); \
        acc[0][2] = fmaf(a0, b2, acc[0][2]); acc[0][3] = fmaf(a0, b3, acc[0][3]); \
        acc[1][0] = fmaf(a1, b0, acc[1][0]); acc[1][1] = fmaf(a1, b1, acc[1][1]); \
        acc[1][2] = fmaf(a1, b2, acc[1][2]); acc[1][3] = fmaf(a1, b3, acc[1][3]); \
        acc[2][0] = fmaf(a2, b0, acc[2][0]); acc[2][1] = fmaf(a2, b1, acc[2][1]); \
        acc[2][2] = fmaf(a2, b2, acc[2][2]); acc[2][3] = fmaf(a2, b3, acc[2][3]); \
        acc[3][0] = fmaf(a3, b0, acc[3][0]); acc[3][1] = fmaf(a3, b1, acc[3][1]); \
        acc[3][2] = fmaf(a3, b2, acc[3][2]); acc[3][3] = fmaf(a3, b3, acc[3][3]); \
    }                                                                         \
    __syncthreads();

// conv1: C[64 oc][3136 px] = W[64][147] @ im2col(crops)  (k=7, s=4, pad_lo=1)
__global__ void k_conv1(const float* __restrict__ W) {
    const int K = 147;
    int img = blockIdx.z;
    int n0 = blockIdx.x * 64;
    __shared__ float As[16][64];
    __shared__ float Bs[16][64];
    int tid = threadIdx.x;
    int tx4 = (tid & 15) * 4, ty4 = (tid >> 4) * 4;
    float acc[4][4] = {};
    const float* cr = g_crops + (size_t)img * 3 * CROP_ * CROP_;

    for (int k0 = 0; k0 < K; k0 += 16) {
        for (int i = tid; i < 64 * 16; i += 256) {
            int mm = i >> 4, kk = k0 + (i & 15);
            As[i & 15][mm] = (kk < K) ? W[mm * K + kk] : 0.f;
        }
        for (int i = tid; i < 16 * 64; i += 256) {
            int k = i >> 6, nn = i & 63, kk = k0 + k;
            float vv = 0.f;
            if (kk < K) {
                int cch = kk / 49; int rr = kk - cch * 49;
                int ky = rr / 7, kx = rr - ky * 7;
                int pxl = n0 + nn; int oy = pxl / 56, ox = pxl - oy * 56;
                int iy = oy * 4 + ky - 1, ixx = ox * 4 + kx - 1;
                if (iy >= 0 && iy < CROP_ && ixx >= 0 && ixx < CROP_)
                    vv = cr[((size_t)cch * CROP_ + iy) * CROP_ + ixx];
            }
            Bs[k][nn] = vv;
        }
        GEMM_COMPUTE();
    }
    float* op = g_h1 + (size_t)img * 64 * 3136;
#pragma unroll
    for (int i = 0; i < 4; i++)
#pragma unroll
        for (int j = 0; j < 4; j++)
            op[(size_t)(ty4 + i) * 3136 + n0 + tx4 + j] = fmaxf(acc[i][j], 0.f);
}

// conv2: C[256 oc][196 px] = W[256][576] @ im2col(h1)  (k=3, s=4, pad 0)
__global__ void k_conv2(const float* __restrict__ W) {
    const int K = 576;
    int img = blockIdx.z;
    int n0 = blockIdx.x * 64;
    int m0 = blockIdx.y * 64;
    __shared__ float As[16][64];
    __shared__ float Bs[16][64];
    int tid = threadIdx.x;
    int tx4 = (tid & 15) * 4, ty4 = (tid >> 4) * 4;
    float acc[4][4] = {};
    const float* in = g_h1 + (size_t)img * 64 * 3136;

    for (int k0 = 0; k0 < K; k0 += 16) {
        for (int i = tid; i < 64 * 16; i += 256) {
            int mm = i >> 4, kk = k0 + (i & 15);
            As[i & 15][mm] = W[(size_t)(m0 + mm) * K + kk];
        }
        for (int i = tid; i < 16 * 64; i += 256) {
            int k = i >> 6, nn = i & 63, kk = k0 + k;
            int pxl = n0 + nn;
            float vv = 0.f;
            if (pxl < 196) {
                int ic = kk / 9; int rr = kk - ic * 9;
                int ky = rr / 3, kx = rr - ky * 3;
                int oy = pxl / 14, ox = pxl - oy * 14;
                int iy = oy * 4 + ky, ixx = ox * 4 + kx;
                vv = in[((size_t)ic) * 3136 + iy * 56 + ixx];
            }
            Bs[k][nn] = vv;
        }
        GEMM_COMPUTE();
    }
    float* op = g_h2 + (size_t)img * 256 * 196;
#pragma unroll
    for (int i = 0; i < 4; i++)
#pragma unroll
        for (int j = 0; j < 4; j++) {
            int pxl = n0 + tx4 + j;
            if (pxl < 196)
                op[(size_t)(m0 + ty4 + i) * 196 + pxl] = fmaxf(acc[i][j], 0.f);
        }
}

// conv3: C[1024 oc][49 px] = W[1024][2304] @ im2col(h2)  (k=3, s=2, pad_lo=0, pad_hi=1)
__global__ void k_conv3(const float* __restrict__ W) {
    const int K = 2304;
    int img = blockIdx.z;
    int m0 = blockIdx.y * 64;
    __shared__ float As[16][64];
    __shared__ float Bs[16][64];
    int tid = threadIdx.x;
    int tx4 = (tid & 15) * 4, ty4 = (tid >> 4) * 4;
    float acc[4][4] = {};
    const float* in = g_h2 + (size_t)img * 256 * 196;

    for (int k0 = 0; k0 < K; k0 += 16) {
        for (int i = tid; i < 64 * 16; i += 256) {
            int mm = i >> 4, kk = k0 + (i & 15);
            As[i & 15][mm] = W[(size_t)(m0 + mm) * K + kk];
        }
        for (int i = tid; i < 16 * 64; i += 256) {
            int k = i >> 6, nn = i & 63, kk = k0 + k;
            float vv = 0.f;
            if (nn < 49) {
                int ic = kk / 9; int rr = kk - ic * 9;
                int ky = rr / 3, kx = rr - ky * 3;
                int oy = nn / 7, ox = nn - oy * 7;
                int iy = oy * 2 + ky, ixx = ox * 2 + kx;
                if (iy < 14 && ixx < 14)
                    vv = in[((size_t)ic) * 196 + iy * 14 + ixx];
            }
            Bs[k][nn] = vv;
        }
        GEMM_COMPUTE();
    }
    float* op = g_h3 + (size_t)img * 1024 * 49;
#pragma unroll
    for (int i = 0; i < 4; i++)
#pragma unroll
        for (int j = 0; j < 4; j++) {
            int pxl = tx4 + j;
            if (pxl < 49)
                op[(size_t)(m0 + ty4 + i) * 49 + pxl] = fmaxf(acc[i][j], 0.f);
        }
}

// ---------------- tokens: [img][50][1024] = transpose(h3) + CLS mean + pos ----------------
__global__ void k_tokens(const float* __restrict__ pos) {
    int img = blockIdx.x;
    int d = threadIdx.x;           // 1024 threads
    const float* h = g_h3 + ((size_t)img * 1024 + d) * 49;
    float* tk = g_tok + (size_t)img * 50 * 1024;
    float s = 0.f;
#pragma unroll 7
    for (int t = 0; t < 49; t++) {
        float v = h[t];
        s += v;
        tk[(t + 1) * 1024 + d] = v + pos[(t + 1) * 1024 + d];
    }
    tk[d] = s * (1.f / 49.f) + pos[d];
}

// ---------------- K/V projections: C[19200][1024] = tok @ W ----------------
__global__ void k_gemm_tok(const float* __restrict__ W, int which) {
    int m0 = blockIdx.y * 64, n0 = blockIdx.x * 64;
    __shared__ float As[16][64];
    __shared__ float Bs[16][64];
    int tid = threadIdx.x;
    int tx4 = (tid & 15) * 4, ty4 = (tid >> 4) * 4;
    float acc[4][4] = {};
    float* C = which ? g_v : g_k;

    for (int k0 = 0; k0 < 1024; k0 += 16) {
        for (int i = tid; i < 64 * 16; i += 256) {
            int mm = i >> 4, kk = k0 + (i & 15);
            As[i & 15][mm] = g_tok[(size_t)(m0 + mm) * 1024 + kk];
        }
        for (int i = tid; i < 16 * 64; i += 256) {
            int k = i >> 6, nn = i & 63;
            Bs[k][nn] = W[(size_t)(k0 + k) * 1024 + n0 + nn];
        }
        GEMM_COMPUTE();
    }
#pragma unroll
    for (int i = 0; i < 4; i++)
#pragma unroll
        for (int j = 0; j < 4; j++)
            C[(size_t)(m0 + ty4 + i) * 1024 + n0 + tx4 + j] = acc[i][j];
}

// ---------------- q projection (CLS token only) ----------------
__global__ void k_q(const float* __restrict__ wq) {
    __shared__ float cls[1024];
    int img = blockIdx.x, tid = threadIdx.x;   // 256
    const float* tk = g_tok + (size_t)img * 50 * 1024;
    for (int i = tid; i < 1024; i += 256) cls[i] = tk[i];
    __syncthreads();
    float4 acc = {0.f, 0.f, 0.f, 0.f};
    const float4* w4 = (const float4*)wq;
    for (int d = 0; d < 1024; d++) {
        float cv = cls[d];
        float4 w = w4[(size_t)d * 256 + tid];
        acc.x = fmaf(cv, w.x, acc.x); acc.y = fmaf(cv, w.y, acc.y);
        acc.z = fmaf(cv, w.z, acc.z); acc.w = fmaf(cv, w.w, acc.w);
    }
    ((float4*)(g_q + (size_t)img * 1024))[tid] = acc;
}

// ---------------- attention + output projection ----------------
__global__ void k_attn(const float* __restrict__ wo) {
    __shared__ float qs[1024];
    __shared__ float sc[50];
    __shared__ float pr[50];
    __shared__ float ctx[1024];
    int img = blockIdx.x, tid = threadIdx.x;   // 256
    for (int i = tid; i < 1024; i += 256) qs[i] = g_q[(size_t)img * 1024 + i];
    __syncthreads();

    int wid = tid >> 5, lid = tid & 31;
    for (int t = wid; t < 50; t += 8) {
        const float* kr = g_k + ((size_t)img * 50 + t) * 1024;
        float s = 0.f;
        for (int d = lid; d < 1024; d += 32) s = fmaf(qs[d], kr[d], s);
#pragma unroll
        for (int o = 16; o > 0; o >>= 1) s += __shfl_xor_sync(0xffffffffu, s, o);
        if (lid == 0) sc[t] = s * 0.03125f;   // DIM^-0.5 = 1/32
    }
    __syncthreads();
    if (tid == 0) {
        float mx = -1e30f;
        for (int t = 0; t < 50; t++) mx = fmaxf(mx, sc[t]);
        float sum = 0.f;
        for (int t = 0; t < 50; t++) { float e = expf(sc[t] - mx); pr[t] = e; sum += e; }
        float inv = 1.f / sum;
        for (int t = 0; t < 50; t++) pr[t] *= inv;
    }
    __syncthreads();
    {
        float4 acc = {0.f, 0.f, 0.f, 0.f};
        const float4* v4 = (const float4*)(g_v + (size_t)img * 50 * 1024);
        for (int t = 0; t < 50; t++) {
            float p = pr[t];
            float4 v = v4[t * 256 + tid];
            acc.x = fmaf(p, v.x, acc.x); acc.y = fmaf(p, v.y, acc.y);
            acc.z = fmaf(p, v.z, acc.z); acc.w = fmaf(p, v.w, acc.w);
        }
        ((float4*)ctx)[tid] = acc;
    }
    __syncthreads();
    {
        float4 acc = {0.f, 0.f, 0.f, 0.f};
        const float4* w4 = (const float4*)wo;
        for (int d = 0; d < 1024; d++) {
            float cv = ctx[d];
            float4 w = w4[(size_t)d * 256 + tid];
            acc.x = fmaf(cv, w.x, acc.x); acc.y = fmaf(cv, w.y, acc.y);
            acc.z = fmaf(cv, w.z, acc.z); acc.w = fmaf(cv, w.w, acc.w);
        }
        ((float4*)(g_emb + (size_t)img * 1024))[tid] = acc;
    }
}

// ---------------- momentum fusion ----------------
__global__ void k_fuse(const float* __restrict__ bdd,
                       const float* __restrict__ mom_p,
                       float* __restrict__ out) {
    int n = blockIdx.x, d = threadIdx.x;  // 64 blocks x 1024 threads
    float mom = *mom_p;
    float e = bdd[d];
    const int order[6] = {2, 0, 1, 5, 3, 4};
#pragma unroll
    for (int i = 0; i < 6; i++) {
        int c = order[i];
        if (g_valid[n * 6 + c])
            e = mom * e + (1.f - mom) * g_emb[((size_t)(n * 6 + c)) * 1024 + d];
    }
    out[(size_t)n * 1024 + d] = e;
}

// ---------------- launch ----------------
extern "C" void kernel_launch(void* const* d_in, const int* in_sizes, int n_in,
                              void* d_out, int out_size) {
    const float* camera_imgs = (const float*)d_in[0];
    const float* pred_boxes  = (const float*)d_in[1];
    const float* img_aug     = (const float*)d_in[2];
    const float* lidar_aug   = (const float*)d_in[3];
    const float* l2i         = (const float*)d_in[4];
    const float* momentum    = (const float*)d_in[5];
    const float* bdd         = (const float*)d_in[6];
    const float* theta_w     = (const float*)d_in[7];
    const float* theta_b     = (const float*)d_in[8];
    const float* conv1       = (const float*)d_in[9];
    const float* conv2       = (const float*)d_in[10];
    const float* conv3       = (const float*)d_in[11];
    const float* pos         = (const float*)d_in[12];
    const float* wq          = (const float*)d_in[13];
    const float* wk          = (const float*)d_in[14];
    const float* wv          = (const float*)d_in[15];
    const float* wo          = (const float*)d_in[16];

    k_setup<<<(NIMG + 127) / 128, 128>>>(pred_boxes, lidar_aug, l2i, img_aug, theta_w, theta_b);
    k_sample<<<dim3((CROP_ * CROP_ + 255) / 256, NIMG), 256>>>(camera_imgs);
    k_conv1<<<dim3(49, 1, NIMG), 256>>>(conv1);
    k_conv2<<<dim3(4, 4, NIMG), 256>>>(conv2);
    k_conv3<<<dim3(1, 16, NIMG), 256>>>(conv3);
    k_tokens<<<NIMG, 1024>>>(pos);
    k_gemm_tok<<<dim3(16, 300), 256>>>(wk, 0);
    k_gemm_tok<<<dim3(16, 300), 256>>>(wv, 1);
    k_q<<<NIMG, 256>>>(wq);
    k_attn<<<NIMG, 256>>>(wo);
    k_fuse<<<NBOX, 1024>>>(bdd, momentum, (float*)d_out);
}

// round 4
// speedup vs baseline: 1.0529x; 1.0529x over previous
#include <cuda_runtime.h>
#include <math.h>

#define NB_   32
#define NC_   6
#define NIMG  384
#define NBOX  64
#define CROP_ 224
#define IMG_H_ 512
#define IMG_W_ 1408
#define DIM_  1024

// ---------------- scratch (device globals; no allocation) ----------------
__device__ float g_theta[NIMG * 6];
__device__ int   g_valid[NIMG];
__device__ float g_crops[NIMG * 3 * CROP_ * CROP_];
__device__ float g_h1[NIMG * 64 * 56 * 56];
__device__ float g_h2[NIMG * 256 * 14 * 14];
__device__ float g_h3[NIMG * 1024 * 49];
__device__ float g_tok[NIMG * 50 * 1024];
__device__ float g_k[NIMG * 50 * 1024];
__device__ float g_v[NIMG * 50 * 1024];
__device__ float g_q[NIMG * 1024];
__device__ float g_emb[NIMG * 1024];

// ---------------- stage 0: projection + affine theta ----------------
__global__ void k_setup(const float* __restrict__ pred_boxes,
                        const float* __restrict__ la_m,
                        const float* __restrict__ l2i_m,
                        const float* __restrict__ aug_m,
                        const float* __restrict__ theta_w,
                        const float* __restrict__ theta_b) {
    int t = blockIdx.x * blockDim.x + threadIdx.x;
    if (t >= NIMG) return;
    int n = t / NC_, c = t % NC_;
    int b = n / NB_, nb = n % NB_;
    const float* pb = pred_boxes + (b * NB_ + nb) * 9;

    float r[4];
#pragma unroll
    for (int i = 0; i < 4; i++) {
        float s = theta_b[i];
#pragma unroll
        for (int j = 0; j < 9; j++) s += theta_w[i * 9 + j] * pb[j];
        r[i] = tanhf(s);
    }

    const float* la = la_m + b * 16;
    float px0 = pb[0] - la[3], py0 = pb[1] - la[7], pz0 = pb[2] - la[11];
    float a00 = la[0], a01 = la[1], a02 = la[2];
    float a10 = la[4], a11 = la[5], a12 = la[6];
    float a20 = la[8], a21 = la[9], a22 = la[10];
    float det = a00 * (a11 * a22 - a12 * a21) - a01 * (a10 * a22 - a12 * a20)
              + a02 * (a10 * a21 - a11 * a20);
    float id = 1.f / det;
    float i00 = (a11 * a22 - a12 * a21) * id, i01 = (a02 * a21 - a01 * a22) * id, i02 = (a01 * a12 - a02 * a11) * id;
    float i10 = (a12 * a20 - a10 * a22) * id, i11 = (a00 * a22 - a02 * a20) * id, i12 = (a02 * a10 - a00 * a12) * id;
    float i20 = (a10 * a21 - a11 * a20) * id, i21 = (a01 * a20 - a00 * a21) * id, i22 = (a00 * a11 - a01 * a10) * id;
    float px = i00 * px0 + i01 * py0 + i02 * pz0;
    float py = i10 * px0 + i11 * py0 + i12 * pz0;
    float pz = i20 * px0 + i21 * py0 + i22 * pz0;

    const float* m = l2i_m + (b * NC_ + c) * 16;
    float qx = m[0] * px + m[1] * py + m[2] * pz + m[3];
    float qy = m[4] * px + m[5] * py + m[6] * pz + m[7];
    float qz = m[8] * px + m[9] * py + m[10] * pz + m[11];
    float z = fminf(fmaxf(qz, 1e-5f), 100000.f);
    float x = qx / z, y = qy / z;
    const float* g = aug_m + (b * NC_ + c) * 16;
    float u = g[0] * x + g[1] * y + g[2] * z + g[3];
    float v = g[4] * x + g[5] * y + g[6] * z + g[7];
    int on = (v < (float)IMG_H_) && (v >= 0.f) && (u < (float)IMG_W_) && (u >= 0.f);
    float ty = v / (float)IMG_H_ * 2.f - 1.f;
    float tx = u / (float)IMG_W_ * 2.f - 1.f;

    int idx = n * NC_ + c;
    g_theta[idx * 6 + 0] = r[0]; g_theta[idx * 6 + 1] = r[1]; g_theta[idx * 6 + 2] = tx;
    g_theta[idx * 6 + 3] = r[2]; g_theta[idx * 6 + 4] = r[3]; g_theta[idx * 6 + 5] = ty;
    g_valid[idx] = on;
}

// ---------------- stage 1: bilinear grid sample -> crops ----------------
__global__ void k_sample(const float* __restrict__ imgs) {
    int img = blockIdx.y;
    int p = blockIdx.x * blockDim.x + threadIdx.x;
    if (p >= CROP_ * CROP_) return;
    int oy = p / CROP_, ox = p - oy * CROP_;
    const float* th = g_theta + img * 6;
    float gx = (2.f * ox + 1.f) / CROP_ - 1.f;
    float gy = (2.f * oy + 1.f) / CROP_ - 1.f;
    float grx = th[0] * gx + th[1] * gy + th[2];
    float gry = th[3] * gx + th[4] * gy + th[5];
    float ix = ((grx + 1.f) * IMG_W_ - 1.f) * 0.5f;
    float iy = ((gry + 1.f) * IMG_H_ - 1.f) * 0.5f;
    float x0 = floorf(ix), y0 = floorf(iy);
    float wx = ix - x0, wy = iy - y0;
    float x1 = x0 + 1.f, y1 = y0 + 1.f;

    int n = img / NC_, c = img - n * NC_, b = n / NB_;
    const float* base = imgs + (size_t)(b * NC_ + c) * 3 * IMG_H_ * IMG_W_;

    int xi0 = (int)fminf(fmaxf(x0, 0.f), (float)(IMG_W_ - 1));
    int xi1 = (int)fminf(fmaxf(x1, 0.f), (float)(IMG_W_ - 1));
    int yi0 = (int)fminf(fmaxf(y0, 0.f), (float)(IMG_H_ - 1));
    int yi1 = (int)fminf(fmaxf(y1, 0.f), (float)(IMG_H_ - 1));
    float vx0 = (x0 >= 0.f && x0 <= (float)(IMG_W_ - 1)) ? 1.f : 0.f;
    float vx1 = (x1 >= 0.f && x1 <= (float)(IMG_W_ - 1)) ? 1.f : 0.f;
    float vy0 = (y0 >= 0.f && y0 <= (float)(IMG_H_ - 1)) ? 1.f : 0.f;
    float vy1 = (y1 >= 0.f && y1 <= (float)(IMG_H_ - 1)) ? 1.f : 0.f;
    float w00 = (1.f - wx) * (1.f - wy) * vx0 * vy0;
    float w01 = wx * (1.f - wy) * vx1 * vy0;
    float w10 = (1.f - wx) * wy * vx0 * vy1;
    float w11 = wx * wy * vx1 * vy1;

#pragma unroll
    for (int ch = 0; ch < 3; ch++) {
        const float* ib = base + (size_t)ch * IMG_H_ * IMG_W_;
        float v00 = ib[yi0 * IMG_W_ + xi0];
        float v01 = ib[yi0 * IMG_W_ + xi1];
        float v10 = ib[yi1 * IMG_W_ + xi0];
        float v11 = ib[yi1 * IMG_W_ + xi1];
        g_crops[(((size_t)img * 3 + ch) * CROP_ + oy) * CROP_ + ox] =
            v00 * w00 + v01 * w01 + v10 * w10 + v11 * w11;
    }
}

// ---------------- 8x8 / 4x8 microtile compute steps ----------------
// As stride 140 (TM=128) or 72 (TM=64); Bs stride 136.
__device__ __forceinline__ void mm8x8(const float* __restrict__ As,
                                      const float* __restrict__ Bs,
                                      float acc[8][8], int ty8, int tx8) {
#pragma unroll
    for (int k = 0; k < 8; k++) {
        float a[8], b[8];
        *(float4*)&a[0] = *(const float4*)&As[k * 140 + ty8];
        *(float4*)&a[4] = *(const float4*)&As[k * 140 + ty8 + 4];
        *(float4*)&b[0] = *(const float4*)&Bs[k * 136 + tx8];
        *(float4*)&b[4] = *(const float4*)&Bs[k * 136 + tx8 + 4];
#pragma unroll
        for (int i = 0; i < 8; i++)
#pragma unroll
            for (int j = 0; j < 8; j++)
                acc[i][j] = fmaf(a[i], b[j], acc[i][j]);
    }
}

__device__ __forceinline__ void mm4x8(const float* __restrict__ As,
                                      const float* __restrict__ Bs,
                                      float acc[4][8], int ty4, int tx8) {
#pragma unroll
    for (int k = 0; k < 8; k++) {
        float a[4], b[8];
        *(float4*)&a[0] = *(const float4*)&As[k * 72 + ty4];
        *(float4*)&b[0] = *(const float4*)&Bs[k * 136 + tx8];
        *(float4*)&b[4] = *(const float4*)&Bs[k * 136 + tx8 + 4];
#pragma unroll
        for (int i = 0; i < 4; i++)
#pragma unroll
            for (int j = 0; j < 8; j++)
                acc[i][j] = fmaf(a[i], b[j], acc[i][j]);
    }
}

// ======================= conv1: 64x128 tile =========================
// C[64][3136] per img = W[64][147] @ im2col(crops), k=7 s=4 pad_lo=1
__global__ __launch_bounds__(256, 2) void k_conv1(const float* __restrict__ W) {
    __shared__ __align__(16) float As[2][8 * 72];
    __shared__ __align__(16) float Bs[2][8 * 136];
    const int tid = threadIdx.x;
    const int img = blockIdx.z;
    const int n0 = blockIdx.x * 128;
    const int tx8 = (tid & 15) * 8, ty4 = (tid >> 4) * 4;
    float acc[4][8] = {};

    // B gather descriptors: thread loads k-row kb, cols nb..nb+3
    const int kb = tid >> 5;
    const int nb = (tid * 4) & 127;
    int oyd[4], oxd[4], okc[4];
#pragma unroll
    for (int j = 0; j < 4; j++) {
        int ng = n0 + nb + j;
        okc[j] = (ng < 3136);
        if (ng >= 3136) ng = 0;
        int oy = ng / 56, ox = ng - oy * 56;
        oyd[j] = oy * 4 - 1;  // includes pad_lo
        oxd[j] = ox * 4 - 1;
    }
    const float* cr = g_crops + (size_t)img * 3 * CROP_ * CROP_;
    // A: thread loads row am, k = (tid&3)*2 + {0,1}
    const int am = tid >> 2;
    const int ak = (tid & 3) * 2;

    float av[2], bv[4];
    const int NCH = 19;  // ceil(147/8)

#define C1_LOADA(K0) {                                                        \
        int kk0 = (K0) + ak;                                                  \
        av[0] = (kk0     < 147) ? W[am * 147 + kk0]     : 0.f;                \
        av[1] = (kk0 + 1 < 147) ? W[am * 147 + kk0 + 1] : 0.f;                \
    }
#define C1_LOADB(K0) {                                                        \
        int kk = (K0) + kb;                                                   \
        if (kk < 147) {                                                       \
            int cch = kk / 49; int rr = kk - cch * 49;                        \
            int ky = rr / 7, kx = rr - ky * 7;                                \
            const float* ib = cr + cch * (CROP_ * CROP_);                     \
            _Pragma("unroll")                                                 \
            for (int j = 0; j < 4; j++) {                                     \
                int iy = oyd[j] + ky, ixx = oxd[j] + kx;                      \
                bv[j] = (okc[j] && iy >= 0 && iy < CROP_ && ixx >= 0 && ixx < CROP_) \
                        ? ib[iy * CROP_ + ixx] : 0.f;                         \
            }                                                                 \
        } else { bv[0] = bv[1] = bv[2] = bv[3] = 0.f; }                       \
    }
#define C1_STORE(BUF) {                                                       \
        As[BUF][(ak + 0) * 72 + am] = av[0];                                  \
        As[BUF][(ak + 1) * 72 + am] = av[1];                                  \
        *(float4*)&Bs[BUF][kb * 136 + nb] = make_float4(bv[0], bv[1], bv[2], bv[3]); \
    }

    C1_LOADA(0); C1_LOADB(0); C1_STORE(0);
    __syncthreads();
#pragma unroll 1
    for (int ch = 0; ch < NCH; ch++) {
        bool more = (ch + 1 < NCH);
        if (more) { C1_LOADA((ch + 1) * 8); C1_LOADB((ch + 1) * 8); }
        mm4x8(As[ch & 1], Bs[ch & 1], acc, ty4, tx8);
        if (more) { C1_STORE((ch + 1) & 1); __syncthreads(); }
    }
#undef C1_LOADA
#undef C1_LOADB
#undef C1_STORE

    float* op = g_h1 + (size_t)img * 64 * 3136;
#pragma unroll
    for (int i = 0; i < 4; i++)
#pragma unroll
        for (int j = 0; j < 8; j++) {
            int ng = n0 + tx8 + j;
            if (ng < 3136)
                op[(ty4 + i) * 3136 + ng] = fmaxf(acc[i][j], 0.f);
        }
}

// ======================= conv2: 128x128 tile, N flattened ===========
// C[256][384*196] = W[256][576] @ im2col(h1), k=3 s=4 valid
__global__ __launch_bounds__(256, 2) void k_conv2(const float* __restrict__ W) {
    __shared__ __align__(16) float As[2][8 * 140];
    __shared__ __align__(16) float Bs[2][8 * 136];
    const int tid = threadIdx.x;
    const int n0 = blockIdx.x * 128, m0 = blockIdx.y * 128;
    const int tx8 = (tid & 15) * 8, ty8 = (tid >> 4) * 8;
    float acc[8][8] = {};

    const int kb = tid >> 5;
    const int nb = (tid * 4) & 127;
    int imgd[4], oyd[4], oxd[4];
#pragma unroll
    for (int j = 0; j < 4; j++) {
        int ng = n0 + nb + j;
        int img = ng / 196, pxl = ng - img * 196;
        int oy = pxl / 14, ox = pxl - oy * 14;
        imgd[j] = img * 200704;   // img * 64 * 3136
        oyd[j] = oy * 4; oxd[j] = ox * 4;
    }
    const int am = tid >> 1;
    const int ak = (tid & 1) * 4;
    float4 av; float bv[4];
    const int NCH = 72;  // 576/8

#define C2_LOADA(K0) { av = *(const float4*)&W[(m0 + am) * 576 + (K0) + ak]; }
#define C2_LOADB(K0) {                                                        \
        int kk = (K0) + kb;                                                   \
        int ic = kk / 9; int rr = kk - ic * 9;                                \
        int ky = rr / 3, kx = rr - ky * 3;                                    \
        int off = ic * 3136 + ky * 56 + kx;                                   \
        _Pragma("unroll")                                                     \
        for (int j = 0; j < 4; j++)                                           \
            bv[j] = g_h1[imgd[j] + off + oyd[j] * 56 + oxd[j]];               \
    }
#define C2_STORE(BUF) {                                                       \
        As[BUF][(ak + 0) * 140 + am] = av.x;                                  \
        As[BUF][(ak + 1) * 140 + am] = av.y;                                  \
        As[BUF][(ak + 2) * 140 + am] = av.z;                                  \
        As[BUF][(ak + 3) * 140 + am] = av.w;                                  \
        *(float4*)&Bs[BUF][kb * 136 + nb] = make_float4(bv[0], bv[1], bv[2], bv[3]); \
    }

    C2_LOADA(0); C2_LOADB(0); C2_STORE(0);
    __syncthreads();
#pragma unroll 1
    for (int ch = 0; ch < NCH; ch++) {
        bool more = (ch + 1 < NCH);
        if (more) { C2_LOADA((ch + 1) * 8); C2_LOADB((ch + 1) * 8); }
        mm8x8(As[ch & 1], Bs[ch & 1], acc, ty8, tx8);
        if (more) { C2_STORE((ch + 1) & 1); __syncthreads(); }
    }
#undef C2_LOADA
#undef C2_LOADB
#undef C2_STORE

    int oimg[8], opx[8];
#pragma unroll
    for (int j = 0; j < 8; j++) {
        int ng = n0 + tx8 + j;
        int img = ng / 196;
        oimg[j] = img * 50176;    // img * 256 * 196
        opx[j] = ng - img * 196;
    }
#pragma unroll
    for (int i = 0; i < 8; i++)
#pragma unroll
        for (int j = 0; j < 8; j++)
            g_h2[oimg[j] + (m0 + ty8 + i) * 196 + opx[j]] = fmaxf(acc[i][j], 0.f);
}

// ======================= conv3: 128x128 tile, N flattened ===========
// C[1024][384*49] = W[1024][2304] @ im2col(h2), k=3 s=2 pad_hi=1
__global__ __launch_bounds__(256, 2) void k_conv3(const float* __restrict__ W) {
    __shared__ __align__(16) float As[2][8 * 140];
    __shared__ __align__(16) float Bs[2][8 * 136];
    const int tid = threadIdx.x;
    const int n0 = blockIdx.x * 128, m0 = blockIdx.y * 128;
    const int tx8 = (tid & 15) * 8, ty8 = (tid >> 4) * 8;
    float acc[8][8] = {};

    const int kb = tid >> 5;
    const int nb = (tid * 4) & 127;
    int imgd[4], oyd[4], oxd[4];
#pragma unroll
    for (int j = 0; j < 4; j++) {
        int ng = n0 + nb + j;
        int img = ng / 49, pxl = ng - img * 49;
        int oy = pxl / 7, ox = pxl - oy * 7;
        imgd[j] = img * 50176;    // img * 256 * 196
        oyd[j] = oy * 2; oxd[j] = ox * 2;
    }
    const int am = tid >> 1;
    const int ak = (tid & 1) * 4;
    float4 av; float bv[4];
    const int NCH = 288;  // 2304/8

#define C3_LOADA(K0) { av = *(const float4*)&W[(size_t)(m0 + am) * 2304 + (K0) + ak]; }
#define C3_LOADB(K0) {                                                        \
        int kk = (K0) + kb;                                                   \
        int ic = kk / 9; int rr = kk - ic * 9;                                \
        int ky = rr / 3, kx = rr - ky * 3;                                    \
        int off = ic * 196;                                                   \
        _Pragma("unroll")                                                     \
        for (int j = 0; j < 4; j++) {                                         \
            int iy = oyd[j] + ky, ixx = oxd[j] + kx;                          \
            bv[j] = (iy < 14 && ixx < 14)                                     \
                    ? g_h2[imgd[j] + off + iy * 14 + ixx] : 0.f;              \
        }                                                                     \
    }
#define C3_STORE(BUF) {                                                       \
        As[BUF][(ak + 0) * 140 + am] = av.x;                                  \
        As[BUF][(ak + 1) * 140 + am] = av.y;                                  \
        As[BUF][(ak + 2) * 140 + am] = av.z;                                  \
        As[BUF][(ak + 3) * 140 + am] = av.w;                                  \
        *(float4*)&Bs[BUF][kb * 136 + nb] = make_float4(bv[0], bv[1], bv[2], bv[3]); \
    }

    C3_LOADA(0); C3_LOADB(0); C3_STORE(0);
    __syncthreads();
#pragma unroll 1
    for (int ch = 0; ch < NCH; ch++) {
        bool more = (ch + 1 < NCH);
        if (more) { C3_LOADA((ch + 1) * 8); C3_LOADB((ch + 1) * 8); }
        mm8x8(As[ch & 1], Bs[ch & 1], acc, ty8, tx8);
        if (more) { C3_STORE((ch + 1) & 1); __syncthreads(); }
    }
#undef C3_LOADA
#undef C3_LOADB
#undef C3_STORE

    int oimg[8], opx[8];
#pragma unroll
    for (int j = 0; j < 8; j++) {
        int ng = n0 + tx8 + j;
        int img = ng / 49;
        oimg[j] = img * 50176;    // img * 1024 * 49
        opx[j] = ng - img * 49;
    }
#pragma unroll
    for (int i = 0; i < 8; i++)
#pragma unroll
        for (int j = 0; j < 8; j++)
            g_h3[(size_t)oimg[j] + (m0 + ty8 + i) * 49 + opx[j]] = fmaxf(acc[i][j], 0.f);
}

// ---------------- tokens: [img][50][1024] ----------------
__global__ void k_tokens(const float* __restrict__ pos) {
    int img = blockIdx.x;
    int d = threadIdx.x;
    const float* h = g_h3 + ((size_t)img * 1024 + d) * 49;
    float* tk = g_tok + (size_t)img * 50 * 1024;
    float s = 0.f;
#pragma unroll 7
    for (int t = 0; t < 49; t++) {
        float v = h[t];
        s += v;
        tk[(t + 1) * 1024 + d] = v + pos[(t + 1) * 1024 + d];
    }
    tk[d] = s * (1.f / 49.f) + pos[d];
}

// ======================= dense: tok[19200x1024] @ W[1024x1024] ======
template <int WHICH>
__global__ __launch_bounds__(256, 2) void k_dense(const float* __restrict__ W) {
    __shared__ __align__(16) float As[2][8 * 140];
    __shared__ __align__(16) float Bs[2][8 * 136];
    const int tid = threadIdx.x;
    const int n0 = blockIdx.x * 128, m0 = blockIdx.y * 128;
    const int tx8 = (tid & 15) * 8, ty8 = (tid >> 4) * 8;
    float acc[8][8] = {};

    const int kb = tid >> 5;
    const int nb = (tid * 4) & 127;
    const int am = tid >> 1;
    const int ak = (tid & 1) * 4;
    float4 av, bv;
    const int NCH = 128;  // 1024/8

#define KD_LOADA(K0) { av = *(const float4*)&g_tok[(size_t)(m0 + am) * 1024 + (K0) + ak]; }
#define KD_LOADB(K0) { bv = *(const float4*)&W[(size_t)((K0) + kb) * 1024 + n0 + nb]; }
#define KD_STORE(BUF) {                                                       \
        As[BUF][(ak + 0) * 140 + am] = av.x;                                  \
        As[BUF][(ak + 1) * 140 + am] = av.y;                                  \
        As[BUF][(ak + 2) * 140 + am] = av.z;                                  \
        As[BUF][(ak + 3) * 140 + am] = av.w;                                  \
        *(float4*)&Bs[BUF][kb * 136 + nb] = bv;                               \
    }

    KD_LOADA(0); KD_LOADB(0); KD_STORE(0);
    __syncthreads();
#pragma unroll 1
    for (int ch = 0; ch < NCH; ch++) {
        bool more = (ch + 1 < NCH);
        if (more) { KD_LOADA((ch + 1) * 8); KD_LOADB((ch + 1) * 8); }
        mm8x8(As[ch & 1], Bs[ch & 1], acc, ty8, tx8);
        if (more) { KD_STORE((ch + 1) & 1); __syncthreads(); }
    }
#undef KD_LOADA
#undef KD_LOADB
#undef KD_STORE

    float* C = WHICH ? g_v : g_k;
#pragma unroll
    for (int i = 0; i < 8; i++) {
        float* row = C + (size_t)(m0 + ty8 + i) * 1024 + n0 + tx8;
        *(float4*)&row[0] = make_float4(acc[i][0], acc[i][1], acc[i][2], acc[i][3]);
        *(float4*)&row[4] = make_float4(acc[i][4], acc[i][5], acc[i][6], acc[i][7]);
    }
}

// ---------------- q projection (CLS token only) ----------------
__global__ void k_q(const float* __restrict__ wq) {
    __shared__ float cls[1024];
    int img = blockIdx.x, tid = threadIdx.x;   // 256
    const float* tk = g_tok + (size_t)img * 50 * 1024;
    for (int i = tid; i < 1024; i += 256) cls[i] = tk[i];
    __syncthreads();
    float4 acc = {0.f, 0.f, 0.f, 0.f};
    const float4* w4 = (const float4*)wq;
    for (int d = 0; d < 1024; d++) {
        float cv = cls[d];
        float4 w = w4[(size_t)d * 256 + tid];
        acc.x = fmaf(cv, w.x, acc.x); acc.y = fmaf(cv, w.y, acc.y);
        acc.z = fmaf(cv, w.z, acc.z); acc.w = fmaf(cv, w.w, acc.w);
    }
    ((float4*)(g_q + (size_t)img * 1024))[tid] = acc;
}

// ---------------- attention + output projection ----------------
__global__ void k_attn(const float* __restrict__ wo) {
    __shared__ float qs[1024];
    __shared__ float sc[50];
    __shared__ float pr[50];
    __shared__ float ctx[1024];
    int img = blockIdx.x, tid = threadIdx.x;   // 256
    for (int i = tid; i < 1024; i += 256) qs[i] = g_q[(size_t)img * 1024 + i];
    __syncthreads();

    int wid = tid >> 5, lid = tid & 31;
    for (int t = wid; t < 50; t += 8) {
        const float* kr = g_k + ((size_t)img * 50 + t) * 1024;
        float s = 0.f;
        for (int d = lid; d < 1024; d += 32) s = fmaf(qs[d], kr[d], s);
#pragma unroll
        for (int o = 16; o > 0; o >>= 1) s += __shfl_xor_sync(0xffffffffu, s, o);
        if (lid == 0) sc[t] = s * 0.03125f;
    }
    __syncthreads();
    if (tid == 0) {
        float mx = -1e30f;
        for (int t = 0; t < 50; t++) mx = fmaxf(mx, sc[t]);
        float sum = 0.f;
        for (int t = 0; t < 50; t++) { float e = expf(sc[t] - mx); pr[t] = e; sum += e; }
        float inv = 1.f / sum;
        for (int t = 0; t < 50; t++) pr[t] *= inv;
    }
    __syncthreads();
    {
        float4 acc = {0.f, 0.f, 0.f, 0.f};
        const float4* v4 = (const float4*)(g_v + (size_t)img * 50 * 1024);
        for (int t = 0; t < 50; t++) {
            float p = pr[t];
            float4 v = v4[t * 256 + tid];
            acc.x = fmaf(p, v.x, acc.x); acc.y = fmaf(p, v.y, acc.y);
            acc.z = fmaf(p, v.z, acc.z); acc.w = fmaf(p, v.w, acc.w);
        }
        ((float4*)ctx)[tid] = acc;
    }
    __syncthreads();
    {
        float4 acc = {0.f, 0.f, 0.f, 0.f};
        const float4* w4 = (const float4*)wo;
        for (int d = 0; d < 1024; d++) {
            float cv = ctx[d];
            float4 w = w4[(size_t)d * 256 + tid];
            acc.x = fmaf(cv, w.x, acc.x); acc.y = fmaf(cv, w.y, acc.y);
            acc.z = fmaf(cv, w.z, acc.z); acc.w = fmaf(cv, w.w, acc.w);
        }
        ((float4*)(g_emb + (size_t)img * 1024))[tid] = acc;
    }
}

// ---------------- momentum fusion ----------------
__global__ void k_fuse(const float* __restrict__ bdd,
                       const float* __restrict__ mom_p,
                       float* __restrict__ out) {
    int n = blockIdx.x, d = threadIdx.x;
    float mom = *mom_p;
    float e = bdd[d];
    const int order[6] = {2, 0, 1, 5, 3, 4};
#pragma unroll
    for (int i = 0; i < 6; i++) {
        int c = order[i];
        if (g_valid[n * 6 + c])
            e = mom * e + (1.f - mom) * g_emb[((size_t)(n * 6 + c)) * 1024 + d];
    }
    out[(size_t)n * 1024 + d] = e;
}

// ---------------- launch ----------------
extern "C" void kernel_launch(void* const* d_in, const int* in_sizes, int n_in,
                              void* d_out, int out_size) {
    const float* camera_imgs = (const float*)d_in[0];
    const float* pred_boxes  = (const float*)d_in[1];
    const float* img_aug     = (const float*)d_in[2];
    const float* lidar_aug   = (const float*)d_in[3];
    const float* l2i         = (const float*)d_in[4];
    const float* momentum    = (const float*)d_in[5];
    const float* bdd         = (const float*)d_in[6];
    const float* theta_w     = (const float*)d_in[7];
    const float* theta_b     = (const float*)d_in[8];
    const float* conv1       = (const float*)d_in[9];
    const float* conv2       = (const float*)d_in[10];
    const float* conv3       = (const float*)d_in[11];
    const float* pos         = (const float*)d_in[12];
    const float* wq          = (const float*)d_in[13];
    const float* wk          = (const float*)d_in[14];
    const float* wv          = (const float*)d_in[15];
    const float* wo          = (const float*)d_in[16];

    k_setup<<<(NIMG + 127) / 128, 128>>>(pred_boxes, lidar_aug, l2i, img_aug, theta_w, theta_b);
    k_sample<<<dim3((CROP_ * CROP_ + 255) / 256, NIMG), 256>>>(camera_imgs);
    k_conv1<<<dim3(25, 1, NIMG), 256>>>(conv1);
    k_conv2<<<dim3(588, 2), 256>>>(conv2);       // N=384*196=75264, M=256
    k_conv3<<<dim3(147, 8), 256>>>(conv3);       // N=384*49=18816, M=1024
    k_tokens<<<NIMG, 1024>>>(pos);
    k_dense<0><<<dim3(8, 150), 256>>>(wk);       // M=19200, N=1024
    k_dense<1><<<dim3(8, 150), 256>>>(wv);
    k_q<<<NIMG, 256>>>(wq);
    k_attn<<<NIMG, 256>>>(wo);
    k_fuse<<<NBOX, 1024>>>(bdd, momentum, (float*)d_out);
}

// round 6
// speedup vs baseline: 2.8096x; 2.6684x over previous
#include <cuda_runtime.h>
#include <cuda_bf16.h>
#include <math.h>
#include <stdint.h>

#define NB_   32
#define NC_   6
#define NIMG  384
#define NBOX  64
#define CROP_ 224
#define IMG_H_ 512
#define IMG_W_ 1408
#define DIM_  1024

// ---------------- scratch (device globals; no allocation) ----------------
__device__ float g_theta[NIMG * 6];
__device__ int   g_valid[NIMG];
__device__ __align__(16) float g_crops[NIMG * 3 * CROP_ * CROP_];
__device__ __align__(16) float g_h1[NIMG * 64 * 56 * 56];          // conv1 out [img][oc][56][56]
__device__ __align__(16) float g_h2n[NIMG * 196 * 256];            // conv2 out [n][256]
__device__ __align__(16) float g_h3n[NIMG * 49 * 1024];            // conv3 out [n][1024]
__device__ __align__(16) float g_tok[NIMG * 50 * 1024];
__device__ __align__(16) float g_k[NIMG * 50 * 1024];
__device__ __align__(16) float g_v[NIMG * 50 * 1024];
__device__ float g_q[NIMG * 1024];
__device__ float g_emb[NIMG * 1024];

// bf16 hi/lo split buffers
__device__ __align__(16) __nv_bfloat16 g_w2h[256 * 576],   g_w2l[256 * 576];
__device__ __align__(16) __nv_bfloat16 g_w3h[1024 * 2304], g_w3l[1024 * 2304];
__device__ __align__(16) __nv_bfloat16 g_wkth[1024 * 1024], g_wktl[1024 * 1024];
__device__ __align__(16) __nv_bfloat16 g_wvth[1024 * 1024], g_wvtl[1024 * 1024];
__device__ __align__(16) __nv_bfloat16 g_b2h[NIMG * 196 * 576],  g_b2l[NIMG * 196 * 576];
__device__ __align__(16) __nv_bfloat16 g_b3h[NIMG * 49 * 2304],  g_b3l[NIMG * 49 * 2304];
__device__ __align__(16) __nv_bfloat16 g_tokh[NIMG * 50 * 1024], g_tokl[NIMG * 50 * 1024];

// ---------------- PTX helpers (sm_80-portable) ----------------
__device__ __forceinline__ uint32_t smem_u32(const void* p) {
    uint32_t a;
    asm("{ .reg .u64 t; cvta.to.shared.u64 t, %1; cvt.u32.u64 %0, t; }" : "=r"(a) : "l"(p));
    return a;
}
__device__ __forceinline__ void cp16(uint32_t saddr, const void* gptr) {
    asm volatile("cp.async.cg.shared.global [%0], [%1], 16;" :: "r"(saddr), "l"(gptr));
}
#define CP_COMMIT() asm volatile("cp.async.commit_group;" ::: "memory")
#define CP_WAIT1()  asm volatile("cp.async.wait_group 1;" ::: "memory")
#define CP_WAIT0()  asm volatile("cp.async.wait_group 0;" ::: "memory")

__device__ __forceinline__ void ldsm4(uint32_t (&r)[4], uint32_t addr) {
    asm volatile("ldmatrix.sync.aligned.m8n8.x4.shared.b16 {%0,%1,%2,%3}, [%4];"
                 : "=r"(r[0]), "=r"(r[1]), "=r"(r[2]), "=r"(r[3]) : "r"(addr));
}
__device__ __forceinline__ void mma16816(float (&d)[4], const uint32_t (&a)[4],
                                         const uint32_t b0, const uint32_t b1) {
    asm volatile(
        "mma.sync.aligned.m16n8k16.row.col.f32.bf16.bf16.f32 "
        "{%0,%1,%2,%3},{%4,%5,%6,%7},{%8,%9},{%0,%1,%2,%3};"
        : "+f"(d[0]), "+f"(d[1]), "+f"(d[2]), "+f"(d[3])
        : "r"(a[0]), "r"(a[1]), "r"(a[2]), "r"(a[3]), "r"(b0), "r"(b1));
}

// =============== tensor-core split-bf16 GEMM (mma.sync HMMA) ===============
// out[n*OC + m] = sum_k A[m][k]*B[n][k]; A,B given as bf16 hi/lo pairs.
// CTA tile 128x128, K-chunk 32, cp.async double-buffered.
// smem per stage: Ahi,Alo,Bhi,Blo each 128 rows x 40 bf16 (80B stride) = 10240B.
#define STG_BYTES 40960
__global__ __launch_bounds__(256, 1) void k_tgemm(
    const __nv_bfloat16* __restrict__ Ahi, const __nv_bfloat16* __restrict__ Alo,
    const __nv_bfloat16* __restrict__ Bhi, const __nv_bfloat16* __restrict__ Blo,
    int K, int OC, float* __restrict__ out, int relu) {
    extern __shared__ __align__(128) char smem[];
    const uint32_t sbase = smem_u32(smem);
    const int tid = threadIdx.x;
    const int wid = tid >> 5, lane = tid & 31;
    const int m0 = blockIdx.y * 128, n0 = blockIdx.x * 128;
    const int wm = wid & 3, wn = wid >> 2;         // 4 x 2 warp grid
    const int m0w = wm * 32, n0w = wn * 64;

    float acc[2][8][4] = {};

    // stage loads: 512 16B-chunks per matrix (128 rows x 4), 2 per thread
    const int lrow = tid >> 2;           // rows tid/4 and +64
    const int lc = (tid & 3) * 16;       // byte chunk within row (4 x 16B = 32 elems)

#define TG_LOAD(BUF, KC0) {                                                     \
        uint32_t sb = sbase + (BUF) * STG_BYTES;                                \
        _Pragma("unroll")                                                       \
        for (int h = 0; h < 2; h++) {                                           \
            int row = lrow + h * 64;                                            \
            uint32_t so = row * 80 + lc;                                        \
            size_t ga = (size_t)(m0 + row) * K + (KC0) + (lc >> 1);             \
            size_t gb = (size_t)(n0 + row) * K + (KC0) + (lc >> 1);             \
            cp16(sb + so,         Ahi + ga);                                    \
            cp16(sb + 10240 + so, Alo + ga);                                    \
            cp16(sb + 20480 + so, Bhi + gb);                                    \
            cp16(sb + 30720 + so, Blo + gb);                                    \
        }                                                                       \
        CP_COMMIT();                                                            \
    }

    const int nch = K >> 5;
    TG_LOAD(0, 0);

#pragma unroll 1
    for (int ch = 0; ch < nch; ch++) {
        if (ch + 1 < nch) { TG_LOAD((ch + 1) & 1, (ch + 1) * 32); CP_WAIT1(); }
        else              { CP_WAIT0(); }
        __syncthreads();

        const uint32_t st = sbase + (ch & 1) * STG_BYTES;
        const uint32_t aoff = (m0w + (lane & 15)) * 80 + ((lane >> 4) & 1) * 16;
        const uint32_t boff = (n0w + (lane & 7) + ((lane & 16) >> 1)) * 80 + ((lane & 8) << 1);
#pragma unroll
        for (int k16 = 0; k16 < 2; k16++) {
            const uint32_t kb = k16 * 32;
            uint32_t ah[2][4], al[2][4];
            ldsm4(ah[0], st +         aoff + kb);
            ldsm4(ah[1], st +         aoff + 16 * 80 + kb);
            ldsm4(al[0], st + 10240 + aoff + kb);
            ldsm4(al[1], st + 10240 + aoff + 16 * 80 + kb);
            uint32_t bh[4][4], bl[4][4];
#pragma unroll
            for (int njp = 0; njp < 4; njp++) {
                ldsm4(bh[njp], st + 20480 + boff + njp * 16 * 80 + kb);
                ldsm4(bl[njp], st + 30720 + boff + njp * 16 * 80 + kb);
            }
#pragma unroll
            for (int mi = 0; mi < 2; mi++)
#pragma unroll
                for (int njp = 0; njp < 4; njp++) {
                    mma16816(acc[mi][2 * njp],     ah[mi], bh[njp][0], bh[njp][1]);
                    mma16816(acc[mi][2 * njp + 1], ah[mi], bh[njp][2], bh[njp][3]);
                    mma16816(acc[mi][2 * njp],     ah[mi], bl[njp][0], bl[njp][1]);
                    mma16816(acc[mi][2 * njp + 1], ah[mi], bl[njp][2], bl[njp][3]);
                    mma16816(acc[mi][2 * njp],     al[mi], bh[njp][0], bh[njp][1]);
                    mma16816(acc[mi][2 * njp + 1], al[mi], bh[njp][2], bh[njp][3]);
                }
        }
        __syncthreads();
    }
#undef TG_LOAD

    // epilogue: acc frag (mi,nj): element (row = m0w+mi*16+(lane>>2)[+8], col = nj*8+2*(lane&3)+{0,1})
    const int rbase = m0 + m0w + (lane >> 2);
    const int cbase = n0 + n0w + ((lane & 3) << 1);
#pragma unroll
    for (int mi = 0; mi < 2; mi++)
#pragma unroll
        for (int nj = 0; nj < 8; nj++) {
            float* d = acc[mi][nj];
            int row = rbase + mi * 16;
            int col = cbase + nj * 8;
            float v0 = d[0], v1 = d[1], v2 = d[2], v3 = d[3];
            if (relu) {
                v0 = fmaxf(v0, 0.f); v1 = fmaxf(v1, 0.f);
                v2 = fmaxf(v2, 0.f); v3 = fmaxf(v3, 0.f);
            }
            out[(size_t)col * OC + row] = v0;
            out[(size_t)(col + 1) * OC + row] = v1;
            out[(size_t)col * OC + row + 8] = v2;
            out[(size_t)(col + 1) * OC + row + 8] = v3;
        }
}

// ---------------- conversion kernels ----------------
__device__ __forceinline__ void split_bf16(float x, __nv_bfloat16* h, __nv_bfloat16* l) {
    __nv_bfloat16 hi = __float2bfloat16(x);
    *h = hi;
    *l = __float2bfloat16(x - __bfloat162float(hi));
}

__global__ void k_cvt_direct(const float* __restrict__ src,
                             __nv_bfloat16* __restrict__ hi,
                             __nv_bfloat16* __restrict__ lo, int n) {
    int i = blockIdx.x * blockDim.x + threadIdx.x;
    if (i < n) split_bf16(src[i], hi + i, lo + i);
}

// W [k][n] -> Wt hi/lo [n][k]
__global__ void k_cvt_wt(const float* __restrict__ W,
                         __nv_bfloat16* __restrict__ hi,
                         __nv_bfloat16* __restrict__ lo) {
    int i = blockIdx.x * blockDim.x + threadIdx.x;
    int n = i >> 10, k = i & 1023;
    split_bf16(W[k * 1024 + n], hi + i, lo + i);
}

// im2col for conv2: B2[n][k], n=img*196+px, k=ic*9+ky*3+kx, from g_h1 [img][64][56][56]
__global__ void k_im2col2() {
    int i = blockIdx.x * blockDim.x + threadIdx.x;
    if (i >= NIMG * 196 * 144) return;
    int n = i / 144, k4 = i - n * 144;
    int img = n / 196, px = n - img * 196;
    int oy = px / 14, ox = px - oy * 14;
    const float* h1 = g_h1 + (size_t)img * 64 * 3136;
#pragma unroll
    for (int j = 0; j < 4; j++) {
        int k = k4 * 4 + j;
        int ic = k / 9, r = k - ic * 9;
        int ky = r / 3, kx = r - ky * 3;
        float v = h1[ic * 3136 + (oy * 4 + ky) * 56 + ox * 4 + kx];
        size_t o = (size_t)n * 576 + k;
        split_bf16(v, g_b2h + o, g_b2l + o);
    }
}

// im2col for conv3: B3[n][k], n=img*49+px, k=ic*9+r, from g_h2n [img*196+pix][256]
__global__ void k_im2col3() {
    int i = blockIdx.x * blockDim.x + threadIdx.x;
    if (i >= NIMG * 49 * 576) return;
    int n = i / 576, k4 = i - n * 576;
    int img = n / 49, px = n - img * 49;
    int oy = px / 7, ox = px - oy * 7;
#pragma unroll
    for (int j = 0; j < 4; j++) {
        int k = k4 * 4 + j;
        int ic = k / 9;
        int r = k - ic * 9;
        int ky = r / 3, kx = r - ky * 3;
        int iy = oy * 2 + ky, ix = ox * 2 + kx;
        float v = (iy < 14 && ix < 14)
                  ? g_h2n[((size_t)img * 196 + iy * 14 + ix) * 256 + ic] : 0.f;
        size_t o = (size_t)n * 2304 + k;
        split_bf16(v, g_b3h + o, g_b3l + o);
    }
}

// ---------------- stage 0: projection + affine theta ----------------
__global__ void k_setup(const float* __restrict__ pred_boxes,
                        const float* __restrict__ la_m,
                        const float* __restrict__ l2i_m,
                        const float* __restrict__ aug_m,
                        const float* __restrict__ theta_w,
                        const float* __restrict__ theta_b) {
    int t = blockIdx.x * blockDim.x + threadIdx.x;
    if (t >= NIMG) return;
    int n = t / NC_, c = t % NC_;
    int b = n / NB_, nb = n % NB_;
    const float* pb = pred_boxes + (b * NB_ + nb) * 9;

    float r[4];
#pragma unroll
    for (int i = 0; i < 4; i++) {
        float s = theta_b[i];
#pragma unroll
        for (int j = 0; j < 9; j++) s += theta_w[i * 9 + j] * pb[j];
        r[i] = tanhf(s);
    }

    const float* la = la_m + b * 16;
    float px0 = pb[0] - la[3], py0 = pb[1] - la[7], pz0 = pb[2] - la[11];
    float a00 = la[0], a01 = la[1], a02 = la[2];
    float a10 = la[4], a11 = la[5], a12 = la[6];
    float a20 = la[8], a21 = la[9], a22 = la[10];
    float det = a00 * (a11 * a22 - a12 * a21) - a01 * (a10 * a22 - a12 * a20)
              + a02 * (a10 * a21 - a11 * a20);
    float id = 1.f / det;
    float i00 = (a11 * a22 - a12 * a21) * id, i01 = (a02 * a21 - a01 * a22) * id, i02 = (a01 * a12 - a02 * a11) * id;
    float i10 = (a12 * a20 - a10 * a22) * id, i11 = (a00 * a22 - a02 * a20) * id, i12 = (a02 * a10 - a00 * a12) * id;
    float i20 = (a10 * a21 - a11 * a20) * id, i21 = (a01 * a20 - a00 * a21) * id, i22 = (a00 * a11 - a01 * a10) * id;
    float px = i00 * px0 + i01 * py0 + i02 * pz0;
    float py = i10 * px0 + i11 * py0 + i12 * pz0;
    float pz = i20 * px0 + i21 * py0 + i22 * pz0;

    const float* m = l2i_m + (b * NC_ + c) * 16;
    float qx = m[0] * px + m[1] * py + m[2] * pz + m[3];
    float qy = m[4] * px + m[5] * py + m[6] * pz + m[7];
    float qz = m[8] * px + m[9] * py + m[10] * pz + m[11];
    float z = fminf(fmaxf(qz, 1e-5f), 100000.f);
    float x = qx / z, y = qy / z;
    const float* g = aug_m + (b * NC_ + c) * 16;
    float u = g[0] * x + g[1] * y + g[2] * z + g[3];
    float v = g[4] * x + g[5] * y + g[6] * z + g[7];
    int on = (v < (float)IMG_H_) && (v >= 0.f) && (u < (float)IMG_W_) && (u >= 0.f);
    float ty = v / (float)IMG_H_ * 2.f - 1.f;
    float tx = u / (float)IMG_W_ * 2.f - 1.f;

    int idx = n * NC_ + c;
    g_theta[idx * 6 + 0] = r[0]; g_theta[idx * 6 + 1] = r[1]; g_theta[idx * 6 + 2] = tx;
    g_theta[idx * 6 + 3] = r[2]; g_theta[idx * 6 + 4] = r[3]; g_theta[idx * 6 + 5] = ty;
    g_valid[idx] = on;
}

// ---------------- stage 1: bilinear grid sample -> crops ----------------
__global__ void k_sample(const float* __restrict__ imgs) {
    int img = blockIdx.y;
    int p = blockIdx.x * blockDim.x + threadIdx.x;
    if (p >= CROP_ * CROP_) return;
    int oy = p / CROP_, ox = p - oy * CROP_;
    const float* th = g_theta + img * 6;
    float gx = (2.f * ox + 1.f) / CROP_ - 1.f;
    float gy = (2.f * oy + 1.f) / CROP_ - 1.f;
    float grx = th[0] * gx + th[1] * gy + th[2];
    float gry = th[3] * gx + th[4] * gy + th[5];
    float ix = ((grx + 1.f) * IMG_W_ - 1.f) * 0.5f;
    float iy = ((gry + 1.f) * IMG_H_ - 1.f) * 0.5f;
    float x0 = floorf(ix), y0 = floorf(iy);
    float wx = ix - x0, wy = iy - y0;
    float x1 = x0 + 1.f, y1 = y0 + 1.f;

    int n = img / NC_, c = img - n * NC_, b = n / NB_;
    const float* base = imgs + (size_t)(b * NC_ + c) * 3 * IMG_H_ * IMG_W_;

    int xi0 = (int)fminf(fmaxf(x0, 0.f), (float)(IMG_W_ - 1));
    int xi1 = (int)fminf(fmaxf(x1, 0.f), (float)(IMG_W_ - 1));
    int yi0 = (int)fminf(fmaxf(y0, 0.f), (float)(IMG_H_ - 1));
    int yi1 = (int)fminf(fmaxf(y1, 0.f), (float)(IMG_H_ - 1));
    float vx0 = (x0 >= 0.f && x0 <= (float)(IMG_W_ - 1)) ? 1.f : 0.f;
    float vx1 = (x1 >= 0.f && x1 <= (float)(IMG_W_ - 1)) ? 1.f : 0.f;
    float vy0 = (y0 >= 0.f && y0 <= (float)(IMG_H_ - 1)) ? 1.f : 0.f;
    float vy1 = (y1 >= 0.f && y1 <= (float)(IMG_H_ - 1)) ? 1.f : 0.f;
    float w00 = (1.f - wx) * (1.f - wy) * vx0 * vy0;
    float w01 = wx * (1.f - wy) * vx1 * vy0;
    float w10 = (1.f - wx) * wy * vx0 * vy1;
    float w11 = wx * wy * vx1 * vy1;

#pragma unroll
    for (int ch = 0; ch < 3; ch++) {
        const float* ib = base + (size_t)ch * IMG_H_ * IMG_W_;
        float v00 = ib[yi0 * IMG_W_ + xi0];
        float v01 = ib[yi0 * IMG_W_ + xi1];
        float v10 = ib[yi1 * IMG_W_ + xi0];
        float v11 = ib[yi1 * IMG_W_ + xi1];
        g_crops[(((size_t)img * 3 + ch) * CROP_ + oy) * CROP_ + ox] =
            v00 * w00 + v01 * w01 + v10 * w10 + v11 * w11;
    }
}

// ---------------- conv1 (fp32 SGEMM, 64x128 tile) ----------------
__device__ __forceinline__ void mm4x8(const float* __restrict__ As,
                                      const float* __restrict__ Bs,
                                      float acc[4][8], int ty4, int tx8) {
#pragma unroll
    for (int k = 0; k < 8; k++) {
        float a[4], b[8];
        *(float4*)&a[0] = *(const float4*)&As[k * 72 + ty4];
        *(float4*)&b[0] = *(const float4*)&Bs[k * 136 + tx8];
        *(float4*)&b[4] = *(const float4*)&Bs[k * 136 + tx8 + 4];
#pragma unroll
        for (int i = 0; i < 4; i++)
#pragma unroll
            for (int j = 0; j < 8; j++)
                acc[i][j] = fmaf(a[i], b[j], acc[i][j]);
    }
}

__global__ __launch_bounds__(256, 2) void k_conv1(const float* __restrict__ W) {
    __shared__ __align__(16) float As[2][8 * 72];
    __shared__ __align__(16) float Bs[2][8 * 136];
    const int tid = threadIdx.x;
    const int img = blockIdx.z;
    const int n0 = blockIdx.x * 128;
    const int tx8 = (tid & 15) * 8, ty4 = (tid >> 4) * 4;
    float acc[4][8] = {};

    const int kb = tid >> 5;
    const int nb = (tid * 4) & 127;
    int oyd[4], oxd[4], okc[4];
#pragma unroll
    for (int j = 0; j < 4; j++) {
        int ng = n0 + nb + j;
        okc[j] = (ng < 3136);
        if (ng >= 3136) ng = 0;
        int oy = ng / 56, ox = ng - oy * 56;
        oyd[j] = oy * 4 - 1;
        oxd[j] = ox * 4 - 1;
    }
    const float* cr = g_crops + (size_t)img * 3 * CROP_ * CROP_;
    const int am = tid >> 2;
    const int ak = (tid & 3) * 2;

    float av[2], bv[4];
    const int NCH = 19;

#define C1_LOADA(K0) {                                                        \
        int kk0 = (K0) + ak;                                                  \
        av[0] = (kk0     < 147) ? W[am * 147 + kk0]     : 0.f;                \
        av[1] = (kk0 + 1 < 147) ? W[am * 147 + kk0 + 1] : 0.f;                \
    }
#define C1_LOADB(K0) {                                                        \
        int kk = (K0) + kb;                                                   \
        if (kk < 147) {                                                       \
            int cch = kk / 49; int rr = kk - cch * 49;                        \
            int ky = rr / 7, kx = rr - ky * 7;                                \
            const float* ib = cr + cch * (CROP_ * CROP_);                     \
            _Pragma("unroll")                                                 \
            for (int j = 0; j < 4; j++) {                                     \
                int iy = oyd[j] + ky, ixx = oxd[j] + kx;                      \
                bv[j] = (okc[j] && iy >= 0 && iy < CROP_ && ixx >= 0 && ixx < CROP_) \
                        ? ib[iy * CROP_ + ixx] : 0.f;                         \
            }                                                                 \
        } else { bv[0] = bv[1] = bv[2] = bv[3] = 0.f; }                       \
    }
#define C1_STORE(BUF) {                                                       \
        As[BUF][(ak + 0) * 72 + am] = av[0];                                  \
        As[BUF][(ak + 1) * 72 + am] = av[1];                                  \
        *(float4*)&Bs[BUF][kb * 136 + nb] = make_float4(bv[0], bv[1], bv[2], bv[3]); \
    }

    C1_LOADA(0); C1_LOADB(0); C1_STORE(0);
    __syncthreads();
#pragma unroll 1
    for (int ch = 0; ch < NCH; ch++) {
        bool more = (ch + 1 < NCH);
        if (more) { C1_LOADA((ch + 1) * 8); C1_LOADB((ch + 1) * 8); }
        mm4x8(As[ch & 1], Bs[ch & 1], acc, ty4, tx8);
        if (more) { C1_STORE((ch + 1) & 1); __syncthreads(); }
    }
#undef C1_LOADA
#undef C1_LOADB
#undef C1_STORE

    float* op = g_h1 + (size_t)img * 64 * 3136;
#pragma unroll
    for (int i = 0; i < 4; i++)
#pragma unroll
        for (int j = 0; j < 8; j++) {
            int ng = n0 + tx8 + j;
            if (ng < 3136)
                op[(ty4 + i) * 3136 + ng] = fmaxf(acc[i][j], 0.f);
        }
}

// ---------------- tokens from h3n + bf16 split ----------------
__global__ void k_tokens(const float* __restrict__ pos) {
    int img = blockIdx.x;
    int d = threadIdx.x;    // 1024
    float s = 0.f;
    float* tk = g_tok + (size_t)img * 50 * 1024;
    __nv_bfloat16* th = g_tokh + (size_t)img * 50 * 1024;
    __nv_bfloat16* tl = g_tokl + (size_t)img * 50 * 1024;
#pragma unroll 7
    for (int t = 0; t < 49; t++) {
        float v = g_h3n[((size_t)img * 49 + t) * 1024 + d];
        s += v;
        float tv = v + pos[(t + 1) * 1024 + d];
        tk[(t + 1) * 1024 + d] = tv;
        split_bf16(tv, th + (t + 1) * 1024 + d, tl + (t + 1) * 1024 + d);
    }
    float cls = s * (1.f / 49.f) + pos[d];
    tk[d] = cls;
    split_bf16(cls, th + d, tl + d);
}

// ---------------- q projection (CLS token only) ----------------
__global__ void k_q(const float* __restrict__ wq) {
    __shared__ float cls[1024];
    int img = blockIdx.x, tid = threadIdx.x;
    const float* tk = g_tok + (size_t)img * 50 * 1024;
    for (int i = tid; i < 1024; i += 256) cls[i] = tk[i];
    __syncthreads();
    float4 acc = {0.f, 0.f, 0.f, 0.f};
    const float4* w4 = (const float4*)wq;
    for (int d = 0; d < 1024; d++) {
        float cv = cls[d];
        float4 w = w4[(size_t)d * 256 + tid];
        acc.x = fmaf(cv, w.x, acc.x); acc.y = fmaf(cv, w.y, acc.y);
        acc.z = fmaf(cv, w.z, acc.z); acc.w = fmaf(cv, w.w, acc.w);
    }
    ((float4*)(g_q + (size_t)img * 1024))[tid] = acc;
}

// ---------------- attention + output projection ----------------
__global__ void k_attn(const float* __restrict__ wo) {
    __shared__ float qs[1024];
    __shared__ float sc[50];
    __shared__ float pr[50];
    __shared__ float ctx[1024];
    int img = blockIdx.x, tid = threadIdx.x;
    for (int i = tid; i < 1024; i += 256) qs[i] = g_q[(size_t)img * 1024 + i];
    __syncthreads();

    int wid = tid >> 5, lid = tid & 31;
    for (int t = wid; t < 50; t += 8) {
        const float* kr = g_k + ((size_t)img * 50 + t) * 1024;
        float s = 0.f;
        for (int d = lid; d < 1024; d += 32) s = fmaf(qs[d], kr[d], s);
#pragma unroll
        for (int o = 16; o > 0; o >>= 1) s += __shfl_xor_sync(0xffffffffu, s, o);
        if (lid == 0) sc[t] = s * 0.03125f;
    }
    __syncthreads();
    if (tid == 0) {
        float mx = -1e30f;
        for (int t = 0; t < 50; t++) mx = fmaxf(mx, sc[t]);
        float sum = 0.f;
        for (int t = 0; t < 50; t++) { float e = expf(sc[t] - mx); pr[t] = e; sum += e; }
        float inv = 1.f / sum;
        for (int t = 0; t < 50; t++) pr[t] *= inv;
    }
    __syncthreads();
    {
        float4 acc = {0.f, 0.f, 0.f, 0.f};
        const float4* v4 = (const float4*)(g_v + (size_t)img * 50 * 1024);
        for (int t = 0; t < 50; t++) {
            float p = pr[t];
            float4 v = v4[t * 256 + tid];
            acc.x = fmaf(p, v.x, acc.x); acc.y = fmaf(p, v.y, acc.y);
            acc.z = fmaf(p, v.z, acc.z); acc.w = fmaf(p, v.w, acc.w);
        }
        ((float4*)ctx)[tid] = acc;
    }
    __syncthreads();
    {
        float4 acc = {0.f, 0.f, 0.f, 0.f};
        const float4* w4 = (const float4*)wo;
        for (int d = 0; d < 1024; d++) {
            float cv = ctx[d];
            float4 w = w4[(size_t)d * 256 + tid];
            acc.x = fmaf(cv, w.x, acc.x); acc.y = fmaf(cv, w.y, acc.y);
            acc.z = fmaf(cv, w.z, acc.z); acc.w = fmaf(cv, w.w, acc.w);
        }
        ((float4*)(g_emb + (size_t)img * 1024))[tid] = acc;
    }
}

// ---------------- momentum fusion ----------------
__global__ void k_fuse(const float* __restrict__ bdd,
                       const float* __restrict__ mom_p,
                       float* __restrict__ out) {
    int n = blockIdx.x, d = threadIdx.x;
    float mom = *mom_p;
    float e = bdd[d];
    const int order[6] = {2, 0, 1, 5, 3, 4};
#pragma unroll
    for (int i = 0; i < 6; i++) {
        int c = order[i];
        if (g_valid[n * 6 + c])
            e = mom * e + (1.f - mom) * g_emb[((size_t)(n * 6 + c)) * 1024 + d];
    }
    out[(size_t)n * 1024 + d] = e;
}

// ---------------- launch ----------------
extern "C" void kernel_launch(void* const* d_in, const int* in_sizes, int n_in,
                              void* d_out, int out_size) {
    const float* camera_imgs = (const float*)d_in[0];
    const float* pred_boxes  = (const float*)d_in[1];
    const float* img_aug     = (const float*)d_in[2];
    const float* lidar_aug   = (const float*)d_in[3];
    const float* l2i         = (const float*)d_in[4];
    const float* momentum    = (const float*)d_in[5];
    const float* bdd         = (const float*)d_in[6];
    const float* theta_w     = (const float*)d_in[7];
    const float* theta_b     = (const float*)d_in[8];
    const float* conv1       = (const float*)d_in[9];
    const float* conv2       = (const float*)d_in[10];
    const float* conv3       = (const float*)d_in[11];
    const float* pos         = (const float*)d_in[12];
    const float* wq          = (const float*)d_in[13];
    const float* wk          = (const float*)d_in[14];
    const float* wv          = (const float*)d_in[15];
    const float* wo          = (const float*)d_in[16];

    const int TG_SMEM = 2 * STG_BYTES;   // 81920
    static int smem_set = 0;
    if (!smem_set) {
        cudaFuncSetAttribute(k_tgemm, cudaFuncAttributeMaxDynamicSharedMemorySize, TG_SMEM);
        smem_set = 1;
    }

    __nv_bfloat16 *w2h, *w2l, *w3h, *w3l, *wkth, *wktl, *wvth, *wvtl;
    __nv_bfloat16 *b2h, *b2l, *b3h, *b3l, *tokh, *tokl;
    float *h2n, *h3n, *gk, *gv;
    cudaGetSymbolAddress((void**)&w2h, g_w2h);  cudaGetSymbolAddress((void**)&w2l, g_w2l);
    cudaGetSymbolAddress((void**)&w3h, g_w3h);  cudaGetSymbolAddress((void**)&w3l, g_w3l);
    cudaGetSymbolAddress((void**)&wkth, g_wkth); cudaGetSymbolAddress((void**)&wktl, g_wktl);
    cudaGetSymbolAddress((void**)&wvth, g_wvth); cudaGetSymbolAddress((void**)&wvtl, g_wvtl);
    cudaGetSymbolAddress((void**)&b2h, g_b2h);  cudaGetSymbolAddress((void**)&b2l, g_b2l);
    cudaGetSymbolAddress((void**)&b3h, g_b3h);  cudaGetSymbolAddress((void**)&b3l, g_b3l);
    cudaGetSymbolAddress((void**)&tokh, g_tokh); cudaGetSymbolAddress((void**)&tokl, g_tokl);
    cudaGetSymbolAddress((void**)&h2n, g_h2n);  cudaGetSymbolAddress((void**)&h3n, g_h3n);
    cudaGetSymbolAddress((void**)&gk, g_k);     cudaGetSymbolAddress((void**)&gv, g_v);

    k_setup<<<(NIMG + 127) / 128, 128>>>(pred_boxes, lidar_aug, l2i, img_aug, theta_w, theta_b);
    k_sample<<<dim3((CROP_ * CROP_ + 255) / 256, NIMG), 256>>>(camera_imgs);
    k_conv1<<<dim3(25, 1, NIMG), 256>>>(conv1);

    // weight conversions (input-only deps)
    k_cvt_direct<<<(256 * 576 + 255) / 256, 256>>>(conv2, w2h, w2l, 256 * 576);
    k_cvt_direct<<<(1024 * 2304 + 255) / 256, 256>>>(conv3, w3h, w3l, 1024 * 2304);
    k_cvt_wt<<<(1024 * 1024) / 256, 256>>>(wk, wkth, wktl);
    k_cvt_wt<<<(1024 * 1024) / 256, 256>>>(wv, wvth, wvtl);

    // conv2 on tensor cores
    k_im2col2<<<(NIMG * 196 * 144 + 255) / 256, 256>>>();
    k_tgemm<<<dim3(588, 2), 256, TG_SMEM>>>(w2h, w2l, b2h, b2l, 576, 256, h2n, 1);

    // conv3 on tensor cores
    k_im2col3<<<(NIMG * 49 * 576 + 255) / 256, 256>>>();
    k_tgemm<<<dim3(147, 8), 256, TG_SMEM>>>(w3h, w3l, b3h, b3l, 2304, 1024, h3n, 1);

    k_tokens<<<NIMG, 1024>>>(pos);

    // K/V projections on tensor cores
    k_tgemm<<<dim3(150, 8), 256, TG_SMEM>>>(wkth, wktl, tokh, tokl, 1024, 1024, gk, 0);
    k_tgemm<<<dim3(150, 8), 256, TG_SMEM>>>(wvth, wvtl, tokh, tokl, 1024, 1024, gv, 0);

    k_q<<<NIMG, 256>>>(wq);
    k_attn<<<NIMG, 256>>>(wo);
    k_fuse<<<NBOX, 1024>>>(bdd, momentum, (float*)d_out);
}

// round 8
// speedup vs baseline: 2.9395x; 1.0462x over previous
#include <cuda_runtime.h>
#include <cuda_bf16.h>
#include <math.h>
#include <stdint.h>

#define NB_   32
#define NC_   6
#define NIMG  384
#define NBOX  64
#define CROP_ 224
#define IMG_H_ 512
#define IMG_W_ 1408
#define DIM_  1024
#define N1    (NIMG * 3136)      // conv1 output pixels = 1204224
#define K1P   224                // conv1 K padded: 7*7*4(ch padded) = 196 -> 224

// ---------------- scratch (device globals; no allocation) ----------------
__device__ float g_theta[NIMG * 6];
__device__ int   g_valid[NIMG];
// crops: channel-last, ch padded to 4: [img][y][x][4], bf16 hi/lo
__device__ __align__(16) __nv_bfloat16 g_cropsh[(size_t)NIMG * CROP_ * CROP_ * 4];
__device__ __align__(16) __nv_bfloat16 g_cropsl[(size_t)NIMG * CROP_ * CROP_ * 4];
// conv1 im2col: [n][224] bf16 hi/lo
__device__ __align__(16) __nv_bfloat16 g_b1h[(size_t)N1 * K1P];
__device__ __align__(16) __nv_bfloat16 g_b1l[(size_t)N1 * K1P];
__device__ __align__(16) float g_h1[(size_t)N1 * 64];              // conv1 out [n][64]
__device__ __align__(16) float g_h2n[NIMG * 196 * 256];            // conv2 out [n][256]
__device__ __align__(16) float g_h3n[NIMG * 49 * 1024];            // conv3 out [n][1024]
__device__ __align__(16) float g_cls[NIMG * 1024];
__device__ __align__(16) float g_k[NIMG * 50 * 1024];
__device__ __align__(16) float g_v[NIMG * 50 * 1024];
__device__ float g_q[NIMG * 1024];
__device__ float g_emb[NIMG * 1024];

// bf16 hi/lo split buffers (weights + activations)
__device__ __align__(16) __nv_bfloat16 g_w1h[64 * K1P],    g_w1l[64 * K1P];
__device__ __align__(16) __nv_bfloat16 g_w2h[256 * 576],   g_w2l[256 * 576];
__device__ __align__(16) __nv_bfloat16 g_w3h[1024 * 2304], g_w3l[1024 * 2304];
__device__ __align__(16) __nv_bfloat16 g_wkth[1024 * 1024], g_wktl[1024 * 1024];
__device__ __align__(16) __nv_bfloat16 g_wvth[1024 * 1024], g_wvtl[1024 * 1024];
__device__ __align__(16) __nv_bfloat16 g_b2h[NIMG * 196 * 576],  g_b2l[NIMG * 196 * 576];
__device__ __align__(16) __nv_bfloat16 g_b3h[NIMG * 49 * 2304],  g_b3l[NIMG * 49 * 2304];
__device__ __align__(16) __nv_bfloat16 g_tokh[NIMG * 50 * 1024], g_tokl[NIMG * 50 * 1024];

// ---------------- PTX helpers (sm_80-portable) ----------------
__device__ __forceinline__ uint32_t smem_u32(const void* p) {
    uint32_t a;
    asm("{ .reg .u64 t; cvta.to.shared.u64 t, %1; cvt.u32.u64 %0, t; }" : "=r"(a) : "l"(p));
    return a;
}
__device__ __forceinline__ void cp16(uint32_t saddr, const void* gptr) {
    asm volatile("cp.async.cg.shared.global [%0], [%1], 16;" :: "r"(saddr), "l"(gptr));
}
#define CP_COMMIT() asm volatile("cp.async.commit_group;" ::: "memory")
#define CP_WAIT1()  asm volatile("cp.async.wait_group 1;" ::: "memory")
#define CP_WAIT0()  asm volatile("cp.async.wait_group 0;" ::: "memory")

__device__ __forceinline__ void ldsm4(uint32_t (&r)[4], uint32_t addr) {
    asm volatile("ldmatrix.sync.aligned.m8n8.x4.shared.b16 {%0,%1,%2,%3}, [%4];"
                 : "=r"(r[0]), "=r"(r[1]), "=r"(r[2]), "=r"(r[3]) : "r"(addr));
}
__device__ __forceinline__ void mma16816(float (&d)[4], const uint32_t (&a)[4],
                                         const uint32_t b0, const uint32_t b1) {
    asm volatile(
        "mma.sync.aligned.m16n8k16.row.col.f32.bf16.bf16.f32 "
        "{%0,%1,%2,%3},{%4,%5,%6,%7},{%8,%9},{%0,%1,%2,%3};"
        : "+f"(d[0]), "+f"(d[1]), "+f"(d[2]), "+f"(d[3])
        : "r"(a[0]), "r"(a[1]), "r"(a[2]), "r"(a[3]), "r"(b0), "r"(b1));
}

__device__ __forceinline__ void split_bf16(float x, __nv_bfloat16* h, __nv_bfloat16* l) {
    __nv_bfloat16 hi = __float2bfloat16(x);
    *h = hi;
    *l = __float2bfloat16(x - __bfloat162float(hi));
}

// =============== tensor-core split-bf16 GEMM (128x128 tile) ===============
#define STG_BYTES 40960
__global__ __launch_bounds__(256, 1) void k_tgemm(
    const __nv_bfloat16* __restrict__ Ahi, const __nv_bfloat16* __restrict__ Alo,
    const __nv_bfloat16* __restrict__ Bhi, const __nv_bfloat16* __restrict__ Blo,
    int K, int OC, float* __restrict__ out, int relu) {
    extern __shared__ __align__(128) char smem[];
    const uint32_t sbase = smem_u32(smem);
    const int tid = threadIdx.x;
    const int wid = tid >> 5, lane = tid & 31;
    const int m0 = blockIdx.y * 128, n0 = blockIdx.x * 128;
    const int wm = wid & 3, wn = wid >> 2;
    const int m0w = wm * 32, n0w = wn * 64;

    float acc[2][8][4] = {};
    const int lrow = tid >> 2;
    const int lc = (tid & 3) * 16;

#define TG_LOAD(BUF, KC0) {                                                     \
        uint32_t sb = sbase + (BUF) * STG_BYTES;                                \
        _Pragma("unroll")                                                       \
        for (int h = 0; h < 2; h++) {                                           \
            int row = lrow + h * 64;                                            \
            uint32_t so = row * 80 + lc;                                        \
            size_t ga = (size_t)(m0 + row) * K + (KC0) + (lc >> 1);             \
            size_t gb = (size_t)(n0 + row) * K + (KC0) + (lc >> 1);             \
            cp16(sb + so,         Ahi + ga);                                    \
            cp16(sb + 10240 + so, Alo + ga);                                    \
            cp16(sb + 20480 + so, Bhi + gb);                                    \
            cp16(sb + 30720 + so, Blo + gb);                                    \
        }                                                                       \
        CP_COMMIT();                                                            \
    }

    const int nch = K >> 5;
    TG_LOAD(0, 0);

#pragma unroll 1
    for (int ch = 0; ch < nch; ch++) {
        if (ch + 1 < nch) { TG_LOAD((ch + 1) & 1, (ch + 1) * 32); CP_WAIT1(); }
        else              { CP_WAIT0(); }
        __syncthreads();

        const uint32_t st = sbase + (ch & 1) * STG_BYTES;
        const uint32_t aoff = (m0w + (lane & 15)) * 80 + ((lane >> 4) & 1) * 16;
        const uint32_t boff = (n0w + (lane & 7) + ((lane & 16) >> 1)) * 80 + ((lane & 8) << 1);
#pragma unroll
        for (int k16 = 0; k16 < 2; k16++) {
            const uint32_t kb = k16 * 32;
            uint32_t ah[2][4], al[2][4];
            ldsm4(ah[0], st +         aoff + kb);
            ldsm4(ah[1], st +         aoff + 16 * 80 + kb);
            ldsm4(al[0], st + 10240 + aoff + kb);
            ldsm4(al[1], st + 10240 + aoff + 16 * 80 + kb);
            uint32_t bh[4][4], bl[4][4];
#pragma unroll
            for (int njp = 0; njp < 4; njp++) {
                ldsm4(bh[njp], st + 20480 + boff + njp * 16 * 80 + kb);
                ldsm4(bl[njp], st + 30720 + boff + njp * 16 * 80 + kb);
            }
#pragma unroll
            for (int mi = 0; mi < 2; mi++)
#pragma unroll
                for (int njp = 0; njp < 4; njp++) {
                    mma16816(acc[mi][2 * njp],     ah[mi], bh[njp][0], bh[njp][1]);
                    mma16816(acc[mi][2 * njp + 1], ah[mi], bh[njp][2], bh[njp][3]);
                    mma16816(acc[mi][2 * njp],     ah[mi], bl[njp][0], bl[njp][1]);
                    mma16816(acc[mi][2 * njp + 1], ah[mi], bl[njp][2], bl[njp][3]);
                    mma16816(acc[mi][2 * njp],     al[mi], bh[njp][0], bh[njp][1]);
                    mma16816(acc[mi][2 * njp + 1], al[mi], bh[njp][2], bh[njp][3]);
                }
        }
        __syncthreads();
    }
#undef TG_LOAD

    const int rbase = m0 + m0w + (lane >> 2);
    const int cbase = n0 + n0w + ((lane & 3) << 1);
#pragma unroll
    for (int mi = 0; mi < 2; mi++)
#pragma unroll
        for (int nj = 0; nj < 8; nj++) {
            float* d = acc[mi][nj];
            int row = rbase + mi * 16;
            int col = cbase + nj * 8;
            float v0 = d[0], v1 = d[1], v2 = d[2], v3 = d[3];
            if (relu) {
                v0 = fmaxf(v0, 0.f); v1 = fmaxf(v1, 0.f);
                v2 = fmaxf(v2, 0.f); v3 = fmaxf(v3, 0.f);
            }
            out[(size_t)col * OC + row] = v0;
            out[(size_t)(col + 1) * OC + row] = v1;
            out[(size_t)col * OC + row + 8] = v2;
            out[(size_t)(col + 1) * OC + row + 8] = v3;
        }
}

// =============== 64x256-tile variant (for conv1, M=64) ===============
#define STG64 51200
__global__ __launch_bounds__(256) void k_tgemm64(
    const __nv_bfloat16* __restrict__ Ahi, const __nv_bfloat16* __restrict__ Alo,
    const __nv_bfloat16* __restrict__ Bhi, const __nv_bfloat16* __restrict__ Blo,
    int K, float* __restrict__ out) {
    extern __shared__ __align__(128) char smem[];
    const uint32_t sbase = smem_u32(smem);
    const int tid = threadIdx.x;
    const int wid = tid >> 5, lane = tid & 31;
    const int n0 = blockIdx.x * 256;
    const int wm = wid & 1, wn = wid >> 1;     // 2 x 4 warp grid
    const int m0w = wm * 32, n0w = wn * 64;

    float acc[2][8][4] = {};
    const int arow = tid >> 2;
    const int lc = (tid & 3) * 16;

#define TG64_LOAD(BUF, KC0) {                                                   \
        uint32_t sb = sbase + (BUF) * STG64;                                    \
        {                                                                       \
            uint32_t so = arow * 80 + lc;                                       \
            size_t ga = (size_t)arow * K + (KC0) + (lc >> 1);                   \
            cp16(sb + so,        Ahi + ga);                                     \
            cp16(sb + 5120 + so, Alo + ga);                                     \
        }                                                                       \
        _Pragma("unroll")                                                       \
        for (int h = 0; h < 4; h++) {                                           \
            int row = arow + h * 64;                                            \
            uint32_t so = row * 80 + lc;                                        \
            size_t gb = (size_t)(n0 + row) * K + (KC0) + (lc >> 1);             \
            cp16(sb + 10240 + so, Bhi + gb);                                    \
            cp16(sb + 30720 + so, Blo + gb);                                    \
        }                                                                       \
        CP_COMMIT();                                                            \
    }

    const int nch = K >> 5;
    TG64_LOAD(0, 0);

#pragma unroll 1
    for (int ch = 0; ch < nch; ch++) {
        if (ch + 1 < nch) { TG64_LOAD((ch + 1) & 1, (ch + 1) * 32); CP_WAIT1(); }
        else              { CP_WAIT0(); }
        __syncthreads();

        const uint32_t st = sbase + (ch & 1) * STG64;
        const uint32_t aoff = (m0w + (lane & 15)) * 80 + ((lane >> 4) & 1) * 16;
        const uint32_t boff = (n0w + (lane & 7) + ((lane & 16) >> 1)) * 80 + ((lane & 8) << 1);
#pragma unroll
        for (int k16 = 0; k16 < 2; k16++) {
            const uint32_t kb = k16 * 32;
            uint32_t ah[2][4], al[2][4];
            ldsm4(ah[0], st +        aoff + kb);
            ldsm4(ah[1], st +        aoff + 16 * 80 + kb);
            ldsm4(al[0], st + 5120 + aoff + kb);
            ldsm4(al[1], st + 5120 + aoff + 16 * 80 + kb);
            uint32_t bh[4][4], bl[4][4];
#pragma unroll
            for (int njp = 0; njp < 4; njp++) {
                ldsm4(bh[njp], st + 10240 + boff + njp * 16 * 80 + kb);
                ldsm4(bl[njp], st + 30720 + boff + njp * 16 * 80 + kb);
            }
#pragma unroll
            for (int mi = 0; mi < 2; mi++)
#pragma unroll
                for (int njp = 0; njp < 4; njp++) {
                    mma16816(acc[mi][2 * njp],     ah[mi], bh[njp][0], bh[njp][1]);
                    mma16816(acc[mi][2 * njp + 1], ah[mi], bh[njp][2], bh[njp][3]);
                    mma16816(acc[mi][2 * njp],     ah[mi], bl[njp][0], bl[njp][1]);
                    mma16816(acc[mi][2 * njp + 1], ah[mi], bl[njp][2], bl[njp][3]);
                    mma16816(acc[mi][2 * njp],     al[mi], bh[njp][0], bh[njp][1]);
                    mma16816(acc[mi][2 * njp + 1], al[mi], bh[njp][2], bh[njp][3]);
                }
        }
        __syncthreads();
    }
#undef TG64_LOAD

    const int rbase = m0w + (lane >> 2);
    const int cbase = n0 + n0w + ((lane & 3) << 1);
#pragma unroll
    for (int mi = 0; mi < 2; mi++)
#pragma unroll
        for (int nj = 0; nj < 8; nj++) {
            float* d = acc[mi][nj];
            int row = rbase + mi * 16;
            int col = cbase + nj * 8;
            out[(size_t)col * 64 + row] = fmaxf(d[0], 0.f);
            out[(size_t)(col + 1) * 64 + row] = fmaxf(d[1], 0.f);
            out[(size_t)col * 64 + row + 8] = fmaxf(d[2], 0.f);
            out[(size_t)(col + 1) * 64 + row + 8] = fmaxf(d[3], 0.f);
        }
}

// ---------------- weight conversions ----------------
// conv1 W[64][3][7][7] -> [oc][(ky*7+kx)*4+ch], K padded to 224
__global__ void k_cvt_w1(const float* __restrict__ W) {
    int i = blockIdx.x * blockDim.x + threadIdx.x;   // 64*224
    if (i >= 64 * K1P) return;
    int oc = i / K1P, kp = i - oc * K1P;
    float v = 0.f;
    if (kp < 196) {
        int ch = kp & 3, pos = kp >> 2;
        if (ch < 3) v = W[oc * 147 + ch * 49 + pos];
    }
    split_bf16(v, g_w1h + i, g_w1l + i);
}

// conv2 W[256][64][3][3] -> [oc][r*64+ic]
__global__ void k_cvt_w2(const float* __restrict__ W) {
    int i = blockIdx.x * blockDim.x + threadIdx.x;   // 256*576
    if (i >= 256 * 576) return;
    int oc = i / 576, kp = i - oc * 576;
    int r = kp >> 6, ic = kp & 63;
    split_bf16(W[oc * 576 + ic * 9 + r], g_w2h + i, g_w2l + i);
}

// conv3 W[1024][256][3][3] -> [oc][r*256+ic]
__global__ void k_cvt_w3(const float* __restrict__ W) {
    int i = blockIdx.x * blockDim.x + threadIdx.x;   // 1024*2304
    if (i >= 1024 * 2304) return;
    int oc = i / 2304, kp = i - oc * 2304;
    int r = kp >> 8, ic = kp & 255;
    split_bf16(W[(size_t)oc * 2304 + ic * 9 + r], g_w3h + i, g_w3l + i);
}

// W [k][n] -> Wt hi/lo [n][k]
__global__ void k_cvt_wt(const float* __restrict__ W,
                         __nv_bfloat16* __restrict__ hi,
                         __nv_bfloat16* __restrict__ lo) {
    int i = blockIdx.x * blockDim.x + threadIdx.x;
    int n = i >> 10, k = i & 1023;
    split_bf16(W[k * 1024 + n], hi + i, lo + i);
}

// ---------------- im2col kernels (contiguous vector copies) ----------------
// conv1: thread = (n, sub) sub=0..7; sub<7 copies 7x(4 bf16) for ky=sub; sub==7 zero-fills k 196..223
__global__ void k_im2col1() {
    int i = blockIdx.x * blockDim.x + threadIdx.x;
    if (i >= N1 * 8) return;
    int n = i >> 3, sub = i & 7;
    __nv_bfloat16* dh = g_b1h + (size_t)n * K1P;
    __nv_bfloat16* dl = g_b1l + (size_t)n * K1P;
    const uint2 z = {0u, 0u};
    if (sub == 7) {
#pragma unroll
        for (int j = 0; j < 7; j++) {
            *(uint2*)(dh + 196 + j * 4) = z;
            *(uint2*)(dl + 196 + j * 4) = z;
        }
        return;
    }
    int img = n / 3136, px = n - img * 3136;
    int oy = px / 56, ox = px - oy * 56;
    int iy = oy * 4 - 1 + sub;
    int k0 = sub * 28;
    if (iy < 0 || iy >= CROP_) {
#pragma unroll
        for (int kx = 0; kx < 7; kx++) {
            *(uint2*)(dh + k0 + kx * 4) = z;
            *(uint2*)(dl + k0 + kx * 4) = z;
        }
        return;
    }
    const __nv_bfloat16* sh = g_cropsh + ((size_t)(img * CROP_ + iy)) * CROP_ * 4;
    const __nv_bfloat16* sl = g_cropsl + ((size_t)(img * CROP_ + iy)) * CROP_ * 4;
    int ix0 = ox * 4 - 1;
#pragma unroll
    for (int kx = 0; kx < 7; kx++) {
        int ix = ix0 + kx;
        if (ix >= 0 && ix < CROP_) {
            *(uint2*)(dh + k0 + kx * 4) = *(const uint2*)(sh + ix * 4);
            *(uint2*)(dl + k0 + kx * 4) = *(const uint2*)(sl + ix * 4);
        } else {
            *(uint2*)(dh + k0 + kx * 4) = z;
            *(uint2*)(dl + k0 + kx * 4) = z;
        }
    }
}

// conv2: B2[n2][r*64+ic] from h1 [n'][64]; thread handles 8 ic
__global__ void k_im2col2() {
    int i = blockIdx.x * blockDim.x + threadIdx.x;   // 75264*9*8
    if (i >= NIMG * 196 * 72) return;
    int n2 = i / 72, rem = i - n2 * 72;
    int r = rem >> 3, ic0 = (rem & 7) * 8;
    int img = n2 / 196, px = n2 - img * 196;
    int oy = px / 14, ox = px - oy * 14;
    int ky = r / 3, kx = r - ky * 3;
    int iy = oy * 4 + ky, ix = ox * 4 + kx;
    const float* src = g_h1 + ((size_t)(img * 3136 + iy * 56 + ix)) * 64 + ic0;
    float4 a = *(const float4*)src;
    float4 b = *(const float4*)(src + 4);
    __nv_bfloat16 h[8], l[8];
    split_bf16(a.x, h + 0, l + 0); split_bf16(a.y, h + 1, l + 1);
    split_bf16(a.z, h + 2, l + 2); split_bf16(a.w, h + 3, l + 3);
    split_bf16(b.x, h + 4, l + 4); split_bf16(b.y, h + 5, l + 5);
    split_bf16(b.z, h + 6, l + 6); split_bf16(b.w, h + 7, l + 7);
    size_t o = (size_t)n2 * 576 + r * 64 + ic0;
    *(uint4*)(g_b2h + o) = *(uint4*)h;
    *(uint4*)(g_b2l + o) = *(uint4*)l;
}

// conv3: B3[n3][r*256+ic] from h2n [n'][256]; thread handles 8 ic
__global__ void k_im2col3() {
    int i = blockIdx.x * blockDim.x + threadIdx.x;   // 18816*9*32
    if (i >= NIMG * 49 * 288) return;
    int n3 = i / 288, rem = i - n3 * 288;
    int r = rem >> 5, ic0 = (rem & 31) * 8;
    int img = n3 / 49, px = n3 - img * 49;
    int oy = px / 7, ox = px - oy * 7;
    int ky = r / 3, kx = r - ky * 3;
    int iy = oy * 2 + ky, ix = ox * 2 + kx;
    __nv_bfloat16 h[8], l[8];
    if (iy < 14 && ix < 14) {
        const float* src = g_h2n + ((size_t)(img * 196 + iy * 14 + ix)) * 256 + ic0;
        float4 a = *(const float4*)src;
        float4 b = *(const float4*)(src + 4);
        split_bf16(a.x, h + 0, l + 0); split_bf16(a.y, h + 1, l + 1);
        split_bf16(a.z, h + 2, l + 2); split_bf16(a.w, h + 3, l + 3);
        split_bf16(b.x, h + 4, l + 4); split_bf16(b.y, h + 5, l + 5);
        split_bf16(b.z, h + 6, l + 6); split_bf16(b.w, h + 7, l + 7);
    } else {
        __nv_bfloat16 z = __float2bfloat16(0.f);
#pragma unroll
        for (int j = 0; j < 8; j++) { h[j] = z; l[j] = z; }
    }
    size_t o = (size_t)n3 * 2304 + r * 256 + ic0;
    *(uint4*)(g_b3h + o) = *(uint4*)h;
    *(uint4*)(g_b3l + o) = *(uint4*)l;
}

// ---------------- stage 0: projection + affine theta ----------------
__global__ void k_setup(const float* __restrict__ pred_boxes,
                        const float* __restrict__ la_m,
                        const float* __restrict__ l2i_m,
                        const float* __restrict__ aug_m,
                        const float* __restrict__ theta_w,
                        const float* __restrict__ theta_b) {
    int t = blockIdx.x * blockDim.x + threadIdx.x;
    if (t >= NIMG) return;
    int n = t / NC_, c = t % NC_;
    int b = n / NB_, nb = n % NB_;
    const float* pb = pred_boxes + (b * NB_ + nb) * 9;

    float r[4];
#pragma unroll
    for (int i = 0; i < 4; i++) {
        float s = theta_b[i];
#pragma unroll
        for (int j = 0; j < 9; j++) s += theta_w[i * 9 + j] * pb[j];
        r[i] = tanhf(s);
    }

    const float* la = la_m + b * 16;
    float px0 = pb[0] - la[3], py0 = pb[1] - la[7], pz0 = pb[2] - la[11];
    float a00 = la[0], a01 = la[1], a02 = la[2];
    float a10 = la[4], a11 = la[5], a12 = la[6];
    float a20 = la[8], a21 = la[9], a22 = la[10];
    float det = a00 * (a11 * a22 - a12 * a21) - a01 * (a10 * a22 - a12 * a20)
              + a02 * (a10 * a21 - a11 * a20);
    float id = 1.f / det;
    float i00 = (a11 * a22 - a12 * a21) * id, i01 = (a02 * a21 - a01 * a22) * id, i02 = (a01 * a12 - a02 * a11) * id;
    float i10 = (a12 * a20 - a10 * a22) * id, i11 = (a00 * a22 - a02 * a20) * id, i12 = (a02 * a10 - a00 * a12) * id;
    float i20 = (a10 * a21 - a11 * a20) * id, i21 = (a01 * a20 - a00 * a21) * id, i22 = (a00 * a11 - a01 * a10) * id;
    float px = i00 * px0 + i01 * py0 + i02 * pz0;
    float py = i10 * px0 + i11 * py0 + i12 * pz0;
    float pz = i20 * px0 + i21 * py0 + i22 * pz0;

    const float* m = l2i_m + (b * NC_ + c) * 16;
    float qx = m[0] * px + m[1] * py + m[2] * pz + m[3];
    float qy = m[4] * px + m[5] * py + m[6] * pz + m[7];
    float qz = m[8] * px + m[9] * py + m[10] * pz + m[11];
    float z = fminf(fmaxf(qz, 1e-5f), 100000.f);
    float x = qx / z, y = qy / z;
    const float* g = aug_m + (b * NC_ + c) * 16;
    float u = g[0] * x + g[1] * y + g[2] * z + g[3];
    float v = g[4] * x + g[5] * y + g[6] * z + g[7];
    int on = (v < (float)IMG_H_) && (v >= 0.f) && (u < (float)IMG_W_) && (u >= 0.f);
    float ty = v / (float)IMG_H_ * 2.f - 1.f;
    float tx = u / (float)IMG_W_ * 2.f - 1.f;

    int idx = n * NC_ + c;
    g_theta[idx * 6 + 0] = r[0]; g_theta[idx * 6 + 1] = r[1]; g_theta[idx * 6 + 2] = tx;
    g_theta[idx * 6 + 3] = r[2]; g_theta[idx * 6 + 4] = r[3]; g_theta[idx * 6 + 5] = ty;
    g_valid[idx] = on;
}

// ---------------- stage 1: grid sample -> channel-last bf16 hi/lo crops ----------------
__global__ void k_sample(const float* __restrict__ imgs) {
    int img = blockIdx.y;
    int p = blockIdx.x * blockDim.x + threadIdx.x;
    if (p >= CROP_ * CROP_) return;
    int oy = p / CROP_, ox = p - oy * CROP_;
    const float* th = g_theta + img * 6;
    float gx = (2.f * ox + 1.f) / CROP_ - 1.f;
    float gy = (2.f * oy + 1.f) / CROP_ - 1.f;
    float grx = th[0] * gx + th[1] * gy + th[2];
    float gry = th[3] * gx + th[4] * gy + th[5];
    float ix = ((grx + 1.f) * IMG_W_ - 1.f) * 0.5f;
    float iy = ((gry + 1.f) * IMG_H_ - 1.f) * 0.5f;
    float x0 = floorf(ix), y0 = floorf(iy);
    float wx = ix - x0, wy = iy - y0;
    float x1 = x0 + 1.f, y1 = y0 + 1.f;

    int n = img / NC_, c = img - n * NC_, b = n / NB_;
    const float* base = imgs + (size_t)(b * NC_ + c) * 3 * IMG_H_ * IMG_W_;

    int xi0 = (int)fminf(fmaxf(x0, 0.f), (float)(IMG_W_ - 1));
    int xi1 = (int)fminf(fmaxf(x1, 0.f), (float)(IMG_W_ - 1));
    int yi0 = (int)fminf(fmaxf(y0, 0.f), (float)(IMG_H_ - 1));
    int yi1 = (int)fminf(fmaxf(y1, 0.f), (float)(IMG_H_ - 1));
    float vx0 = (x0 >= 0.f && x0 <= (float)(IMG_W_ - 1)) ? 1.f : 0.f;
    float vx1 = (x1 >= 0.f && x1 <= (float)(IMG_W_ - 1)) ? 1.f : 0.f;
    float vy0 = (y0 >= 0.f && y0 <= (float)(IMG_H_ - 1)) ? 1.f : 0.f;
    float vy1 = (y1 >= 0.f && y1 <= (float)(IMG_H_ - 1)) ? 1.f : 0.f;
    float w00 = (1.f - wx) * (1.f - wy) * vx0 * vy0;
    float w01 = wx * (1.f - wy) * vx1 * vy0;
    float w10 = (1.f - wx) * wy * vx0 * vy1;
    float w11 = wx * wy * vx1 * vy1;

    union { __nv_bfloat16 b16[4]; uint2 u; } uh, ul;
#pragma unroll
    for (int ch = 0; ch < 3; ch++) {
        const float* ib = base + (size_t)ch * IMG_H_ * IMG_W_;
        float v00 = ib[yi0 * IMG_W_ + xi0];
        float v01 = ib[yi0 * IMG_W_ + xi1];
        float v10 = ib[yi1 * IMG_W_ + xi0];
        float v11 = ib[yi1 * IMG_W_ + xi1];
        float v = v00 * w00 + v01 * w01 + v10 * w10 + v11 * w11;
        split_bf16(v, &uh.b16[ch], &ul.b16[ch]);
    }
    uh.b16[3] = __float2bfloat16(0.f);
    ul.b16[3] = __float2bfloat16(0.f);
    size_t o = ((size_t)(img * CROP_ + oy) * CROP_ + ox) * 4;
    *(uint2*)(g_cropsh + o) = uh.u;
    *(uint2*)(g_cropsl + o) = ul.u;
}

// ---------------- tokens from h3n + bf16 split (cls fp32) ----------------
__global__ void k_tokens(const float* __restrict__ pos) {
    int img = blockIdx.x;
    int d = threadIdx.x;    // 1024
    float s = 0.f;
    __nv_bfloat16* th = g_tokh + (size_t)img * 50 * 1024;
    __nv_bfloat16* tl = g_tokl + (size_t)img * 50 * 1024;
#pragma unroll 7
    for (int t = 0; t < 49; t++) {
        float v = g_h3n[((size_t)img * 49 + t) * 1024 + d];
        s += v;
        float tv = v + pos[(t + 1) * 1024 + d];
        split_bf16(tv, th + (t + 1) * 1024 + d, tl + (t + 1) * 1024 + d);
    }
    float cls = s * (1.f / 49.f) + pos[d];
    g_cls[(size_t)img * 1024 + d] = cls;
    split_bf16(cls, th + d, tl + d);
}

// ---------------- q projection (CLS token only) ----------------
__global__ void k_q(const float* __restrict__ wq) {
    __shared__ float cls[1024];
    int img = blockIdx.x, tid = threadIdx.x;
    for (int i = tid; i < 1024; i += 256) cls[i] = g_cls[(size_t)img * 1024 + i];
    __syncthreads();
    float4 acc = {0.f, 0.f, 0.f, 0.f};
    const float4* w4 = (const float4*)wq;
    for (int d = 0; d < 1024; d++) {
        float cv = cls[d];
        float4 w = w4[(size_t)d * 256 + tid];
        acc.x = fmaf(cv, w.x, acc.x); acc.y = fmaf(cv, w.y, acc.y);
        acc.z = fmaf(cv, w.z, acc.z); acc.w = fmaf(cv, w.w, acc.w);
    }
    ((float4*)(g_q + (size_t)img * 1024))[tid] = acc;
}

// ---------------- attention + output projection ----------------
__global__ void k_attn(const float* __restrict__ wo) {
    __shared__ float qs[1024];
    __shared__ float sc[50];
    __shared__ float pr[50];
    __shared__ float ctx[1024];
    int img = blockIdx.x, tid = threadIdx.x;
    for (int i = tid; i < 1024; i += 256) qs[i] = g_q[(size_t)img * 1024 + i];
    __syncthreads();

    int wid = tid >> 5, lid = tid & 31;
    for (int t = wid; t < 50; t += 8) {
        const float* kr = g_k + ((size_t)img * 50 + t) * 1024;
        float s = 0.f;
        for (int d = lid; d < 1024; d += 32) s = fmaf(qs[d], kr[d], s);
#pragma unroll
        for (int o = 16; o > 0; o >>= 1) s += __shfl_xor_sync(0xffffffffu, s, o);
        if (lid == 0) sc[t] = s * 0.03125f;
    }
    __syncthreads();
    if (tid == 0) {
        float mx = -1e30f;
        for (int t = 0; t < 50; t++) mx = fmaxf(mx, sc[t]);
        float sum = 0.f;
        for (int t = 0; t < 50; t++) { float e = expf(sc[t] - mx); pr[t] = e; sum += e; }
        float inv = 1.f / sum;
        for (int t = 0; t < 50; t++) pr[t] *= inv;
    }
    __syncthreads();
    {
        float4 acc = {0.f, 0.f, 0.f, 0.f};
        const float4* v4 = (const float4*)(g_v + (size_t)img * 50 * 1024);
        for (int t = 0; t < 50; t++) {
            float p = pr[t];
            float4 v = v4[t * 256 + tid];
            acc.x = fmaf(p, v.x, acc.x); acc.y = fmaf(p, v.y, acc.y);
            acc.z = fmaf(p, v.z, acc.z); acc.w = fmaf(p, v.w, acc.w);
        }
        ((float4*)ctx)[tid] = acc;
    }
    __syncthreads();
    {
        float4 acc = {0.f, 0.f, 0.f, 0.f};
        const float4* w4 = (const float4*)wo;
        for (int d = 0; d < 1024; d++) {
            float cv = ctx[d];
            float4 w = w4[(size_t)d * 256 + tid];
            acc.x = fmaf(cv, w.x, acc.x); acc.y = fmaf(cv, w.y, acc.y);
            acc.z = fmaf(cv, w.z, acc.z); acc.w = fmaf(cv, w.w, acc.w);
        }
        ((float4*)(g_emb + (size_t)img * 1024))[tid] = acc;
    }
}

// ---------------- momentum fusion ----------------
__global__ void k_fuse(const float* __restrict__ bdd,
                       const float* __restrict__ mom_p,
                       float* __restrict__ out) {
    int n = blockIdx.x, d = threadIdx.x;
    float mom = *mom_p;
    float e = bdd[d];
    const int order[6] = {2, 0, 1, 5, 3, 4};
#pragma unroll
    for (int i = 0; i < 6; i++) {
        int c = order[i];
        if (g_valid[n * 6 + c])
            e = mom * e + (1.f - mom) * g_emb[((size_t)(n * 6 + c)) * 1024 + d];
    }
    out[(size_t)n * 1024 + d] = e;
}

// ---------------- launch ----------------
extern "C" void kernel_launch(void* const* d_in, const int* in_sizes, int n_in,
                              void* d_out, int out_size) {
    const float* camera_imgs = (const float*)d_in[0];
    const float* pred_boxes  = (const float*)d_in[1];
    const float* img_aug     = (const float*)d_in[2];
    const float* lidar_aug   = (const float*)d_in[3];
    const float* l2i         = (const float*)d_in[4];
    const float* momentum    = (const float*)d_in[5];
    const float* bdd         = (const float*)d_in[6];
    const float* theta_w     = (const float*)d_in[7];
    const float* theta_b     = (const float*)d_in[8];
    const float* conv1       = (const float*)d_in[9];
    const float* conv2       = (const float*)d_in[10];
    const float* conv3       = (const float*)d_in[11];
    const float* pos         = (const float*)d_in[12];
    const float* wq          = (const float*)d_in[13];
    const float* wk          = (const float*)d_in[14];
    const float* wv          = (const float*)d_in[15];
    const float* wo          = (const float*)d_in[16];

    const int TG_SMEM = 2 * STG_BYTES;   // 81920
    const int TG64_SMEM = 2 * STG64;     // 102400
    static int smem_set = 0;
    if (!smem_set) {
        cudaFuncSetAttribute(k_tgemm, cudaFuncAttributeMaxDynamicSharedMemorySize, TG_SMEM);
        cudaFuncSetAttribute(k_tgemm64, cudaFuncAttributeMaxDynamicSharedMemorySize, TG64_SMEM);
        smem_set = 1;
    }

    __nv_bfloat16 *w1h, *w1l, *w2h, *w2l, *w3h, *w3l, *wkth, *wktl, *wvth, *wvtl;
    __nv_bfloat16 *b1h, *b1l, *b2h, *b2l, *b3h, *b3l, *tokh, *tokl;
    float *h1, *h2n, *h3n, *gk, *gv;
    cudaGetSymbolAddress((void**)&w1h, g_w1h);  cudaGetSymbolAddress((void**)&w1l, g_w1l);
    cudaGetSymbolAddress((void**)&w2h, g_w2h);  cudaGetSymbolAddress((void**)&w2l, g_w2l);
    cudaGetSymbolAddress((void**)&w3h, g_w3h);  cudaGetSymbolAddress((void**)&w3l, g_w3l);
    cudaGetSymbolAddress((void**)&wkth, g_wkth); cudaGetSymbolAddress((void**)&wktl, g_wktl);
    cudaGetSymbolAddress((void**)&wvth, g_wvth); cudaGetSymbolAddress((void**)&wvtl, g_wvtl);
    cudaGetSymbolAddress((void**)&b1h, g_b1h);  cudaGetSymbolAddress((void**)&b1l, g_b1l);
    cudaGetSymbolAddress((void**)&b2h, g_b2h);  cudaGetSymbolAddress((void**)&b2l, g_b2l);
    cudaGetSymbolAddress((void**)&b3h, g_b3h);  cudaGetSymbolAddress((void**)&b3l, g_b3l);
    cudaGetSymbolAddress((void**)&tokh, g_tokh); cudaGetSymbolAddress((void**)&tokl, g_tokl);
    cudaGetSymbolAddress((void**)&h1, g_h1);
    cudaGetSymbolAddress((void**)&h2n, g_h2n);  cudaGetSymbolAddress((void**)&h3n, g_h3n);
    cudaGetSymbolAddress((void**)&gk, g_k);     cudaGetSymbolAddress((void**)&gv, g_v);

    k_setup<<<(NIMG + 127) / 128, 128>>>(pred_boxes, lidar_aug, l2i, img_aug, theta_w, theta_b);
    k_sample<<<dim3((CROP_ * CROP_ + 255) / 256, NIMG), 256>>>(camera_imgs);

    // weight conversions (input-only deps)
    k_cvt_w1<<<(64 * K1P + 255) / 256, 256>>>(conv1);
    k_cvt_w2<<<(256 * 576 + 255) / 256, 256>>>(conv2);
    k_cvt_w3<<<(1024 * 2304 + 255) / 256, 256>>>(conv3);
    k_cvt_wt<<<(1024 * 1024) / 256, 256>>>(wk, wkth, wktl);
    k_cvt_wt<<<(1024 * 1024) / 256, 256>>>(wv, wvth, wvtl);

    // conv1 on tensor cores
    k_im2col1<<<(N1 * 8 + 255) / 256, 256>>>();
    k_tgemm64<<<N1 / 256, 256, TG64_SMEM>>>(w1h, w1l, b1h, b1l, K1P, h1);

    // conv2 on tensor cores
    k_im2col2<<<(NIMG * 196 * 72 + 255) / 256, 256>>>();
    k_tgemm<<<dim3(588, 2), 256, TG_SMEM>>>(w2h, w2l, b2h, b2l, 576, 256, h2n, 1);

    // conv3 on tensor cores
    k_im2col3<<<(NIMG * 49 * 288 + 255) / 256, 256>>>();
    k_tgemm<<<dim3(147, 8), 256, TG_SMEM>>>(w3h, w3l, b3h, b3l, 2304, 1024, h3n, 1);

    k_tokens<<<NIMG, 1024>>>(pos);

    // K/V projections on tensor cores
    k_tgemm<<<dim3(150, 8), 256, TG_SMEM>>>(wkth, wktl, tokh, tokl, 1024, 1024, gk, 0);
    k_tgemm<<<dim3(150, 8), 256, TG_SMEM>>>(wvth, wvtl, tokh, tokl, 1024, 1024, gv, 0);

    k_q<<<NIMG, 256>>>(wq);
    k_attn<<<NIMG, 256>>>(wo);
    k_fuse<<<NBOX, 1024>>>(bdd, momentum, (float*)d_out);
}

// round 12
// speedup vs baseline: 2.9725x; 1.0112x over previous
#include <cuda_runtime.h>
#include <cuda_bf16.h>
#include <math.h>
#include <stdint.h>

#define NB_   32
#define NC_   6
#define NIMG  384
#define NBOX  64
#define CROP_ 224
#define IMG_H_ 512
#define IMG_W_ 1408
#define N1    (NIMG * 3136)
#define K1P   224            // conv1 K padded: 7*7*4(ch padded) = 196 -> 224

// ---------------- scratch (device globals; no allocation) ----------------
__device__ float g_theta[NIMG * 6];
__device__ int   g_valid[NIMG];
// crops: channel-last, ch padded to 4: [img][y][x][4], bf16 hi/lo
__device__ __align__(16) __nv_bfloat16 g_cropsh[(size_t)NIMG * CROP_ * CROP_ * 4];
__device__ __align__(16) __nv_bfloat16 g_cropsl[(size_t)NIMG * CROP_ * CROP_ * 4];
__device__ __align__(16) __nv_bfloat16 g_b1h[(size_t)N1 * K1P];
__device__ __align__(16) __nv_bfloat16 g_b1l[(size_t)N1 * K1P];
__device__ __align__(16) __nv_bfloat16 g_h1h[(size_t)N1 * 64], g_h1l[(size_t)N1 * 64];
__device__ __align__(16) __nv_bfloat16 g_h2h[NIMG * 196 * 256], g_h2l[NIMG * 196 * 256];
__device__ __align__(16) float g_h3n[NIMG * 49 * 1024];
__device__ __align__(16) float g_k[NIMG * 50 * 1024];
__device__ __align__(16) float g_v[NIMG * 50 * 1024];
__device__ __align__(16) float g_q[NIMG * 1024];
__device__ __align__(16) float g_emb[NIMG * 1024];

__device__ __align__(16) __nv_bfloat16 g_w1h[64 * K1P],    g_w1l[64 * K1P];
__device__ __align__(16) __nv_bfloat16 g_w2h[256 * 576],   g_w2l[256 * 576];
__device__ __align__(16) __nv_bfloat16 g_w3h[1024 * 2304], g_w3l[1024 * 2304];
__device__ __align__(16) __nv_bfloat16 g_wqth[1024 * 1024], g_wqtl[1024 * 1024];
__device__ __align__(16) __nv_bfloat16 g_wkth[1024 * 1024], g_wktl[1024 * 1024];
__device__ __align__(16) __nv_bfloat16 g_wvth[1024 * 1024], g_wvtl[1024 * 1024];
__device__ __align__(16) __nv_bfloat16 g_woth[1024 * 1024], g_wotl[1024 * 1024];
__device__ __align__(16) __nv_bfloat16 g_b2h[NIMG * 196 * 576],  g_b2l[NIMG * 196 * 576];
__device__ __align__(16) __nv_bfloat16 g_b3h[NIMG * 49 * 2304],  g_b3l[NIMG * 49 * 2304];
__device__ __align__(16) __nv_bfloat16 g_tokh[NIMG * 50 * 1024], g_tokl[NIMG * 50 * 1024];
__device__ __align__(16) __nv_bfloat16 g_clsh[NIMG * 1024], g_clsl[NIMG * 1024];
__device__ __align__(16) __nv_bfloat16 g_ctxh[NIMG * 1024], g_ctxl[NIMG * 1024];

// ---------------- PTX helpers (sm_80-portable) ----------------
__device__ __forceinline__ uint32_t smem_u32(const void* p) {
    uint32_t a;
    asm("{ .reg .u64 t; cvta.to.shared.u64 t, %1; cvt.u32.u64 %0, t; }" : "=r"(a) : "l"(p));
    return a;
}
__device__ __forceinline__ void cp16(uint32_t saddr, const void* gptr) {
    asm volatile("cp.async.cg.shared.global [%0], [%1], 16;" :: "r"(saddr), "l"(gptr));
}
#define CP_COMMIT() asm volatile("cp.async.commit_group;" ::: "memory")
#define CP_WAIT1()  asm volatile("cp.async.wait_group 1;" ::: "memory")
#define CP_WAIT0()  asm volatile("cp.async.wait_group 0;" ::: "memory")

__device__ __forceinline__ void ldsm4(uint32_t (&r)[4], uint32_t addr) {
    asm volatile("ldmatrix.sync.aligned.m8n8.x4.shared.b16 {%0,%1,%2,%3}, [%4];"
                 : "=r"(r[0]), "=r"(r[1]), "=r"(r[2]), "=r"(r[3]) : "r"(addr));
}
__device__ __forceinline__ void mma16816(float (&d)[4], const uint32_t (&a)[4],
                                         const uint32_t b0, const uint32_t b1) {
    asm volatile(
        "mma.sync.aligned.m16n8k16.row.col.f32.bf16.bf16.f32 "
        "{%0,%1,%2,%3},{%4,%5,%6,%7},{%8,%9},{%0,%1,%2,%3};"
        : "+f"(d[0]), "+f"(d[1]), "+f"(d[2]), "+f"(d[3])
        : "r"(a[0]), "r"(a[1]), "r"(a[2]), "r"(a[3]), "r"(b0), "r"(b1));
}
__device__ __forceinline__ void split_bf16(float x, __nv_bfloat16* h, __nv_bfloat16* l) {
    __nv_bfloat16 hi = __float2bfloat16(x);
    *h = hi;
    *l = __float2bfloat16(x - __bfloat162float(hi));
}

// common mma compute step on one stage
#define MMA_STAGE(st, AL_OFF, BH_OFF, BL_OFF)                                   \
    {                                                                           \
        const uint32_t aoff = (m0w + (lane & 15)) * 80 + ((lane >> 4) & 1) * 16;\
        const uint32_t boff = (n0w + (lane & 7) + ((lane & 16) >> 1)) * 80 + ((lane & 8) << 1); \
        _Pragma("unroll")                                                       \
        for (int k16 = 0; k16 < 2; k16++) {                                     \
            const uint32_t kb = k16 * 32;                                       \
            uint32_t ah[2][4], al[2][4];                                        \
            ldsm4(ah[0], (st) +            aoff + kb);                          \
            ldsm4(ah[1], (st) +            aoff + 16 * 80 + kb);                \
            ldsm4(al[0], (st) + (AL_OFF) + aoff + kb);                          \
            ldsm4(al[1], (st) + (AL_OFF) + aoff + 16 * 80 + kb);                \
            uint32_t bh[4][4], bl[4][4];                                        \
            _Pragma("unroll")                                                   \
            for (int njp = 0; njp < 4; njp++) {                                 \
                ldsm4(bh[njp], (st) + (BH_OFF) + boff + njp * 16 * 80 + kb);    \
                ldsm4(bl[njp], (st) + (BL_OFF) + boff + njp * 16 * 80 + kb);    \
            }                                                                   \
            _Pragma("unroll")                                                   \
            for (int mi = 0; mi < 2; mi++)                                      \
                _Pragma("unroll")                                               \
                for (int njp = 0; njp < 4; njp++) {                             \
                    mma16816(acc[mi][2 * njp],     ah[mi], bh[njp][0], bh[njp][1]); \
                    mma16816(acc[mi][2 * njp + 1], ah[mi], bh[njp][2], bh[njp][3]); \
                    mma16816(acc[mi][2 * njp],     ah[mi], bl[njp][0], bl[njp][1]); \
                    mma16816(acc[mi][2 * njp + 1], ah[mi], bl[njp][2], bl[njp][3]); \
                    mma16816(acc[mi][2 * njp],     al[mi], bh[njp][0], bh[njp][1]); \
                    mma16816(acc[mi][2 * njp + 1], al[mi], bh[njp][2], bh[njp][3]); \
                }                                                               \
        }                                                                       \
    }

// =============== generic split-bf16 GEMM (128x128 tile) ===============
// mode 0: fp32 out; 1: fp32+relu; 2: relu + split-bf16 out (outh/outl)
#define STG_BYTES 40960
__global__ __launch_bounds__(256, 1) void k_tgemm(
    const __nv_bfloat16* __restrict__ Ahi, const __nv_bfloat16* __restrict__ Alo,
    const __nv_bfloat16* __restrict__ Bhi, const __nv_bfloat16* __restrict__ Blo,
    int K, int OC, float* __restrict__ out,
    __nv_bfloat16* __restrict__ outh, __nv_bfloat16* __restrict__ outl, int mode) {
    extern __shared__ __align__(128) char smem[];
    const uint32_t sbase = smem_u32(smem);
    const int tid = threadIdx.x;
    const int wid = tid >> 5, lane = tid & 31;
    const int m0 = blockIdx.y * 128, n0 = blockIdx.x * 128;
    const int wm = wid & 3, wn = wid >> 2;
    const int m0w = wm * 32, n0w = wn * 64;

    float acc[2][8][4] = {};
    const int lrow = tid >> 2;
    const int lc = (tid & 3) * 16;

#define TG_LOAD(BUF, KC0) {                                                     \
        uint32_t sb = sbase + (BUF) * STG_BYTES;                                \
        _Pragma("unroll")                                                       \
        for (int h = 0; h < 2; h++) {                                           \
            int row = lrow + h * 64;                                            \
            uint32_t so = row * 80 + lc;                                        \
            size_t ga = (size_t)(m0 + row) * K + (KC0) + (lc >> 1);             \
            size_t gb = (size_t)(n0 + row) * K + (KC0) + (lc >> 1);             \
            cp16(sb + so,         Ahi + ga);                                    \
            cp16(sb + 10240 + so, Alo + ga);                                    \
            cp16(sb + 20480 + so, Bhi + gb);                                    \
            cp16(sb + 30720 + so, Blo + gb);                                    \
        }                                                                       \
        CP_COMMIT();                                                            \
    }

    const int nch = K >> 5;
    TG_LOAD(0, 0);
#pragma unroll 1
    for (int ch = 0; ch < nch; ch++) {
        if (ch + 1 < nch) { TG_LOAD((ch + 1) & 1, (ch + 1) * 32); CP_WAIT1(); }
        else              { CP_WAIT0(); }
        __syncthreads();
        const uint32_t st = sbase + (ch & 1) * STG_BYTES;
        MMA_STAGE(st, 10240, 20480, 30720);
        __syncthreads();
    }
#undef TG_LOAD

    const int rbase = m0 + m0w + (lane >> 2);
    const int cbase = n0 + n0w + ((lane & 3) << 1);
#pragma unroll
    for (int mi = 0; mi < 2; mi++)
#pragma unroll
        for (int nj = 0; nj < 8; nj++) {
            float* d = acc[mi][nj];
            int row = rbase + mi * 16;
            int col = cbase + nj * 8;
#pragma unroll
            for (int e = 0; e < 4; e++) {
                int r = row + (e >> 1) * 8;
                int c = col + (e & 1);
                float v = d[e];
                if (mode >= 1) v = fmaxf(v, 0.f);
                size_t o = (size_t)c * OC + r;
                if (mode == 2) split_bf16(v, outh + o, outl + o);
                else out[o] = v;
            }
        }
}

// =============== 64x256-tile variant (conv1; h1 split output) ===============
#define STG64 51200
__global__ __launch_bounds__(256) void k_tgemm64(
    const __nv_bfloat16* __restrict__ Ahi, const __nv_bfloat16* __restrict__ Alo,
    const __nv_bfloat16* __restrict__ Bhi, const __nv_bfloat16* __restrict__ Blo,
    int K) {
    extern __shared__ __align__(128) char smem[];
    const uint32_t sbase = smem_u32(smem);
    const int tid = threadIdx.x;
    const int wid = tid >> 5, lane = tid & 31;
    const int n0 = blockIdx.x * 256;
    const int wm = wid & 1, wn = wid >> 1;     // 2 x 4 warp grid
    const int m0w = wm * 32, n0w = wn * 64;

    float acc[2][8][4] = {};
    const int arow = tid >> 2;
    const int lc = (tid & 3) * 16;

#define TG64_LOAD(BUF, KC0) {                                                   \
        uint32_t sb = sbase + (BUF) * STG64;                                    \
        {                                                                       \
            uint32_t so = arow * 80 + lc;                                       \
            size_t ga = (size_t)arow * K + (KC0) + (lc >> 1);                   \
            cp16(sb + so,        Ahi + ga);                                     \
            cp16(sb + 5120 + so, Alo + ga);                                     \
        }                                                                       \
        _Pragma("unroll")                                                       \
        for (int h = 0; h < 4; h++) {                                           \
            int row = arow + h * 64;                                            \
            uint32_t so = row * 80 + lc;                                        \
            size_t gb = (size_t)(n0 + row) * K + (KC0) + (lc >> 1);             \
            cp16(sb + 10240 + so, Bhi + gb);                                    \
            cp16(sb + 30720 + so, Blo + gb);                                    \
        }                                                                       \
        CP_COMMIT();                                                            \
    }

    const int nch = K >> 5;
    TG64_LOAD(0, 0);
#pragma unroll 1
    for (int ch = 0; ch < nch; ch++) {
        if (ch + 1 < nch) { TG64_LOAD((ch + 1) & 1, (ch + 1) * 32); CP_WAIT1(); }
        else              { CP_WAIT0(); }
        __syncthreads();
        const uint32_t st = sbase + (ch & 1) * STG64;
        MMA_STAGE(st, 5120, 10240, 30720);
        __syncthreads();
    }
#undef TG64_LOAD

    const int rbase = m0w + (lane >> 2);
    const int cbase = n0 + n0w + ((lane & 3) << 1);
#pragma unroll
    for (int mi = 0; mi < 2; mi++)
#pragma unroll
        for (int nj = 0; nj < 8; nj++) {
            float* d = acc[mi][nj];
            int row = rbase + mi * 16;
            int col = cbase + nj * 8;
#pragma unroll
            for (int e = 0; e < 4; e++) {
                int r = row + (e >> 1) * 8;
                int c = col + (e & 1);
                float v = fmaxf(d[e], 0.f);
                size_t o = (size_t)c * 64 + r;
                split_bf16(v, g_h1h + o, g_h1l + o);
            }
        }
}

// ---------------- weight conversions ----------------
__global__ void k_cvt_w1(const float* __restrict__ W) {
    int i = blockIdx.x * blockDim.x + threadIdx.x;
    if (i >= 64 * K1P) return;
    int oc = i / K1P, kp = i - oc * K1P;
    float v = 0.f;
    if (kp < 196) {
        int ch = kp & 3, pos = kp >> 2;
        if (ch < 3) v = W[oc * 147 + ch * 49 + pos];
    }
    split_bf16(v, g_w1h + i, g_w1l + i);
}
__global__ void k_cvt_w2(const float* __restrict__ W) {
    int i = blockIdx.x * blockDim.x + threadIdx.x;
    if (i >= 256 * 576) return;
    int oc = i / 576, kp = i - oc * 576;
    int r = kp >> 6, ic = kp & 63;
    split_bf16(W[oc * 576 + ic * 9 + r], g_w2h + i, g_w2l + i);
}
__global__ void k_cvt_w3(const float* __restrict__ W) {
    int i = blockIdx.x * blockDim.x + threadIdx.x;
    if (i >= 1024 * 2304) return;
    int oc = i / 2304, kp = i - oc * 2304;
    int r = kp >> 8, ic = kp & 255;
    split_bf16(W[(size_t)oc * 2304 + ic * 9 + r], g_w3h + i, g_w3l + i);
}
__global__ void k_cvt_wt(const float* __restrict__ W,
                         __nv_bfloat16* __restrict__ hi,
                         __nv_bfloat16* __restrict__ lo) {
    int i = blockIdx.x * blockDim.x + threadIdx.x;
    int n = i >> 10, k = i & 1023;
    split_bf16(W[k * 1024 + n], hi + i, lo + i);
}

// ---------------- im2col kernels ----------------
// conv1: copy 7x(4ch) per ky from channel-last crops (R8 validated)
__global__ void k_im2col1() {
    int i = blockIdx.x * blockDim.x + threadIdx.x;
    if (i >= N1 * 8) return;
    int n = i >> 3, sub = i & 7;
    __nv_bfloat16* dh = g_b1h + (size_t)n * K1P;
    __nv_bfloat16* dl = g_b1l + (size_t)n * K1P;
    const uint2 z = {0u, 0u};
    if (sub == 7) {
#pragma unroll
        for (int j = 0; j < 7; j++) {
            *(uint2*)(dh + 196 + j * 4) = z;
            *(uint2*)(dl + 196 + j * 4) = z;
        }
        return;
    }
    int img = n / 3136, px = n - img * 3136;
    int oy = px / 56, ox = px - oy * 56;
    int iy = oy * 4 - 1 + sub;
    int k0 = sub * 28;
    if (iy < 0 || iy >= CROP_) {
#pragma unroll
        for (int kx = 0; kx < 7; kx++) {
            *(uint2*)(dh + k0 + kx * 4) = z;
            *(uint2*)(dl + k0 + kx * 4) = z;
        }
        return;
    }
    const __nv_bfloat16* sh = g_cropsh + ((size_t)(img * CROP_ + iy)) * CROP_ * 4;
    const __nv_bfloat16* sl = g_cropsl + ((size_t)(img * CROP_ + iy)) * CROP_ * 4;
    int ix0 = ox * 4 - 1;
#pragma unroll
    for (int kx = 0; kx < 7; kx++) {
        int ix = ix0 + kx;
        if (ix >= 0 && ix < CROP_) {
            *(uint2*)(dh + k0 + kx * 4) = *(const uint2*)(sh + ix * 4);
            *(uint2*)(dl + k0 + kx * 4) = *(const uint2*)(sl + ix * 4);
        } else {
            *(uint2*)(dh + k0 + kx * 4) = z;
            *(uint2*)(dl + k0 + kx * 4) = z;
        }
    }
}

// conv2: b2[n2][r*64+ic] <- h1 split. uint4 = 8 bf16 -> stride q*8 (FIXED)
__global__ void k_im2col2() {
    int i = blockIdx.x * blockDim.x + threadIdx.x;   // n2*72 + r*8 + q
    if (i >= NIMG * 196 * 72) return;
    int n2 = i / 72, rem = i - n2 * 72;
    int r = rem >> 3, q8 = (rem & 7) * 8;
    int img = n2 / 196, px = n2 - img * 196;
    int oy = px / 14, ox = px - oy * 14;
    int iy = oy * 4 + r / 3, ix = ox * 4 + (r % 3);
    size_t src = ((size_t)(img * 3136 + iy * 56 + ix)) * 64 + q8;
    size_t dst = (size_t)n2 * 576 + r * 64 + q8;
    *(uint4*)(g_b2h + dst) = *(const uint4*)(g_h1h + src);
    *(uint4*)(g_b2l + dst) = *(const uint4*)(g_h1l + src);
}
// conv3: b3[n3][r*256+ic] <- h2 split; uint4 = 8 bf16 -> stride q*8 (FIXED)
__global__ void k_im2col3() {
    int i = blockIdx.x * blockDim.x + threadIdx.x;   // n3*288 + r*32 + q
    if (i >= NIMG * 49 * 288) return;
    int n3 = i / 288, rem = i - n3 * 288;
    int r = rem >> 5, q8 = (rem & 31) * 8;
    int img = n3 / 49, px = n3 - img * 49;
    int oy = px / 7, ox = px - oy * 7;
    int iy = oy * 2 + r / 3, ix = ox * 2 + (r % 3);
    size_t dst = (size_t)n3 * 2304 + r * 256 + q8;
    if (iy < 14 && ix < 14) {
        size_t src = ((size_t)(img * 196 + iy * 14 + ix)) * 256 + q8;
        *(uint4*)(g_b3h + dst) = *(const uint4*)(g_h2h + src);
        *(uint4*)(g_b3l + dst) = *(const uint4*)(g_h2l + src);
    } else {
        uint4 z = {0u, 0u, 0u, 0u};
        *(uint4*)(g_b3h + dst) = z;
        *(uint4*)(g_b3l + dst) = z;
    }
}

// ---------------- stage 0: projection + affine theta ----------------
__global__ void k_setup(const float* __restrict__ pred_boxes,
                        const float* __restrict__ la_m,
                        const float* __restrict__ l2i_m,
                        const float* __restrict__ aug_m,
                        const float* __restrict__ theta_w,
                        const float* __restrict__ theta_b) {
    int t = blockIdx.x * blockDim.x + threadIdx.x;
    if (t >= NIMG) return;
    int n = t / NC_, c = t % NC_;
    int b = n / NB_, nb = n % NB_;
    const float* pb = pred_boxes + (b * NB_ + nb) * 9;

    float r[4];
#pragma unroll
    for (int i = 0; i < 4; i++) {
        float s = theta_b[i];
#pragma unroll
        for (int j = 0; j < 9; j++) s += theta_w[i * 9 + j] * pb[j];
        r[i] = tanhf(s);
    }

    const float* la = la_m + b * 16;
    float px0 = pb[0] - la[3], py0 = pb[1] - la[7], pz0 = pb[2] - la[11];
    float a00 = la[0], a01 = la[1], a02 = la[2];
    float a10 = la[4], a11 = la[5], a12 = la[6];
    float a20 = la[8], a21 = la[9], a22 = la[10];
    float det = a00 * (a11 * a22 - a12 * a21) - a01 * (a10 * a22 - a12 * a20)
              + a02 * (a10 * a21 - a11 * a20);
    float id = 1.f / det;
    float i00 = (a11 * a22 - a12 * a21) * id, i01 = (a02 * a21 - a01 * a22) * id, i02 = (a01 * a12 - a02 * a11) * id;
    float i10 = (a12 * a20 - a10 * a22) * id, i11 = (a00 * a22 - a02 * a20) * id, i12 = (a02 * a10 - a00 * a12) * id;
    float i20 = (a10 * a21 - a11 * a20) * id, i21 = (a01 * a20 - a00 * a21) * id, i22 = (a00 * a11 - a01 * a10) * id;
    float px = i00 * px0 + i01 * py0 + i02 * pz0;
    float py = i10 * px0 + i11 * py0 + i12 * pz0;
    float pz = i20 * px0 + i21 * py0 + i22 * pz0;

    const float* m = l2i_m + (b * NC_ + c) * 16;
    float qx = m[0] * px + m[1] * py + m[2] * pz + m[3];
    float qy = m[4] * px + m[5] * py + m[6] * pz + m[7];
    float qz = m[8] * px + m[9] * py + m[10] * pz + m[11];
    float z = fminf(fmaxf(qz, 1e-5f), 100000.f);
    float x = qx / z, y = qy / z;
    const float* g = aug_m + (b * NC_ + c) * 16;
    float u = g[0] * x + g[1] * y + g[2] * z + g[3];
    float v = g[4] * x + g[5] * y + g[6] * z + g[7];
    int on = (v < (float)IMG_H_) && (v >= 0.f) && (u < (float)IMG_W_) && (u >= 0.f);
    float ty = v / (float)IMG_H_ * 2.f - 1.f;
    float tx = u / (float)IMG_W_ * 2.f - 1.f;

    int idx = n * NC_ + c;
    g_theta[idx * 6 + 0] = r[0]; g_theta[idx * 6 + 1] = r[1]; g_theta[idx * 6 + 2] = tx;
    g_theta[idx * 6 + 3] = r[2]; g_theta[idx * 6 + 4] = r[3]; g_theta[idx * 6 + 5] = ty;
    g_valid[idx] = on;
}

// ---------------- stage 1: grid sample -> channel-last split crops ----------------
__global__ void k_sample(const float* __restrict__ imgs) {
    int img = blockIdx.y;
    int p = blockIdx.x * blockDim.x + threadIdx.x;
    if (p >= CROP_ * CROP_) return;
    int oy = p / CROP_, ox = p - oy * CROP_;
    const float* th = g_theta + img * 6;
    float gx = (2.f * ox + 1.f) / CROP_ - 1.f;
    float gy = (2.f * oy + 1.f) / CROP_ - 1.f;
    float grx = th[0] * gx + th[1] * gy + th[2];
    float gry = th[3] * gx + th[4] * gy + th[5];
    float ix = ((grx + 1.f) * IMG_W_ - 1.f) * 0.5f;
    float iy = ((gry + 1.f) * IMG_H_ - 1.f) * 0.5f;
    float x0 = floorf(ix), y0 = floorf(iy);
    float wx = ix - x0, wy = iy - y0;
    float x1 = x0 + 1.f, y1 = y0 + 1.f;

    int n = img / NC_, c = img - n * NC_, b = n / NB_;
    const float* base = imgs + (size_t)(b * NC_ + c) * 3 * IMG_H_ * IMG_W_;

    int xi0 = (int)fminf(fmaxf(x0, 0.f), (float)(IMG_W_ - 1));
    int xi1 = (int)fminf(fmaxf(x1, 0.f), (float)(IMG_W_ - 1));
    int yi0 = (int)fminf(fmaxf(y0, 0.f), (float)(IMG_H_ - 1));
    int yi1 = (int)fminf(fmaxf(y1, 0.f), (float)(IMG_H_ - 1));
    float vx0 = (x0 >= 0.f && x0 <= (float)(IMG_W_ - 1)) ? 1.f : 0.f;
    float vx1 = (x1 >= 0.f && x1 <= (float)(IMG_W_ - 1)) ? 1.f : 0.f;
    float vy0 = (y0 >= 0.f && y0 <= (float)(IMG_H_ - 1)) ? 1.f : 0.f;
    float vy1 = (y1 >= 0.f && y1 <= (float)(IMG_H_ - 1)) ? 1.f : 0.f;
    float w00 = (1.f - wx) * (1.f - wy) * vx0 * vy0;
    float w01 = wx * (1.f - wy) * vx1 * vy0;
    float w10 = (1.f - wx) * wy * vx0 * vy1;
    float w11 = wx * wy * vx1 * vy1;

    union { __nv_bfloat16 b16[4]; uint2 u; } uh, ul;
#pragma unroll
    for (int ch = 0; ch < 3; ch++) {
        const float* ib = base + (size_t)ch * IMG_H_ * IMG_W_;
        float v00 = ib[yi0 * IMG_W_ + xi0];
        float v01 = ib[yi0 * IMG_W_ + xi1];
        float v10 = ib[yi1 * IMG_W_ + xi0];
        float v11 = ib[yi1 * IMG_W_ + xi1];
        float v = v00 * w00 + v01 * w01 + v10 * w10 + v11 * w11;
        split_bf16(v, &uh.b16[ch], &ul.b16[ch]);
    }
    uh.b16[3] = __float2bfloat16(0.f);
    ul.b16[3] = __float2bfloat16(0.f);
    size_t o = ((size_t)(img * CROP_ + oy) * CROP_ + ox) * 4;
    *(uint2*)(g_cropsh + o) = uh.u;
    *(uint2*)(g_cropsl + o) = ul.u;
}

// ---------------- tokens: split tok + contiguous cls split ----------------
__global__ void k_tokens(const float* __restrict__ pos) {
    int img = blockIdx.x;
    int d = threadIdx.x;    // 1024
    float s = 0.f;
    __nv_bfloat16* th = g_tokh + (size_t)img * 50 * 1024;
    __nv_bfloat16* tl = g_tokl + (size_t)img * 50 * 1024;
#pragma unroll 7
    for (int t = 0; t < 49; t++) {
        float v = g_h3n[((size_t)img * 49 + t) * 1024 + d];
        s += v;
        float tv = v + pos[(t + 1) * 1024 + d];
        split_bf16(tv, th + (t + 1) * 1024 + d, tl + (t + 1) * 1024 + d);
    }
    float cls = s * (1.f / 49.f) + pos[d];
    __nv_bfloat16 ch_, cl_;
    split_bf16(cls, &ch_, &cl_);
    th[d] = ch_; tl[d] = cl_;
    g_clsh[(size_t)img * 1024 + d] = ch_;
    g_clsl[(size_t)img * 1024 + d] = cl_;
}

// ---------------- attention core: scores + softmax + ctx (split out) ----------------
__global__ void k_attn(int dummy) {
    __shared__ float qs[1024];
    __shared__ float sc[50];
    __shared__ float pr[50];
    int img = blockIdx.x, tid = threadIdx.x;   // 256
    for (int i = tid; i < 1024; i += 256) qs[i] = g_q[(size_t)img * 1024 + i];
    __syncthreads();

    int wid = tid >> 5, lid = tid & 31;
    for (int t = wid; t < 50; t += 8) {
        const float* kr = g_k + ((size_t)img * 50 + t) * 1024;
        float s = 0.f;
        for (int d = lid; d < 1024; d += 32) s = fmaf(qs[d], kr[d], s);
#pragma unroll
        for (int o = 16; o > 0; o >>= 1) s += __shfl_xor_sync(0xffffffffu, s, o);
        if (lid == 0) sc[t] = s * 0.03125f;
    }
    __syncthreads();
    if (tid == 0) {
        float mx = -1e30f;
        for (int t = 0; t < 50; t++) mx = fmaxf(mx, sc[t]);
        float sum = 0.f;
        for (int t = 0; t < 50; t++) { float e = expf(sc[t] - mx); pr[t] = e; sum += e; }
        float inv = 1.f / sum;
        for (int t = 0; t < 50; t++) pr[t] *= inv;
    }
    __syncthreads();
    {
        float4 acc = {0.f, 0.f, 0.f, 0.f};
        const float4* v4 = (const float4*)(g_v + (size_t)img * 50 * 1024);
        for (int t = 0; t < 50; t++) {
            float p = pr[t];
            float4 v = v4[t * 256 + tid];
            acc.x = fmaf(p, v.x, acc.x); acc.y = fmaf(p, v.y, acc.y);
            acc.z = fmaf(p, v.z, acc.z); acc.w = fmaf(p, v.w, acc.w);
        }
        size_t o = (size_t)img * 1024 + tid * 4;
        split_bf16(acc.x, g_ctxh + o + 0, g_ctxl + o + 0);
        split_bf16(acc.y, g_ctxh + o + 1, g_ctxl + o + 1);
        split_bf16(acc.z, g_ctxh + o + 2, g_ctxl + o + 2);
        split_bf16(acc.w, g_ctxh + o + 3, g_ctxl + o + 3);
    }
}

// ---------------- momentum fusion ----------------
__global__ void k_fuse(const float* __restrict__ bdd,
                       const float* __restrict__ mom_p,
                       float* __restrict__ out) {
    int n = blockIdx.x, d = threadIdx.x;
    float mom = *mom_p;
    float e = bdd[d];
    const int order[6] = {2, 0, 1, 5, 3, 4};
#pragma unroll
    for (int i = 0; i < 6; i++) {
        int c = order[i];
        if (g_valid[n * 6 + c])
            e = mom * e + (1.f - mom) * g_emb[((size_t)(n * 6 + c)) * 1024 + d];
    }
    out[(size_t)n * 1024 + d] = e;
}

// ---------------- launch ----------------
extern "C" void kernel_launch(void* const* d_in, const int* in_sizes, int n_in,
                              void* d_out, int out_size) {
    const float* camera_imgs = (const float*)d_in[0];
    const float* pred_boxes  = (const float*)d_in[1];
    const float* img_aug     = (const float*)d_in[2];
    const float* lidar_aug   = (const float*)d_in[3];
    const float* l2i         = (const float*)d_in[4];
    const float* momentum    = (const float*)d_in[5];
    const float* bdd         = (const float*)d_in[6];
    const float* theta_w     = (const float*)d_in[7];
    const float* theta_b     = (const float*)d_in[8];
    const float* conv1       = (const float*)d_in[9];
    const float* conv2       = (const float*)d_in[10];
    const float* conv3       = (const float*)d_in[11];
    const float* pos         = (const float*)d_in[12];
    const float* wq          = (const float*)d_in[13];
    const float* wk          = (const float*)d_in[14];
    const float* wv          = (const float*)d_in[15];
    const float* wo          = (const float*)d_in[16];

    const int TG_SMEM = 2 * STG_BYTES;   // 81920
    const int TG64_SMEM = 2 * STG64;     // 102400
    static int smem_set = 0;
    if (!smem_set) {
        cudaFuncSetAttribute(k_tgemm, cudaFuncAttributeMaxDynamicSharedMemorySize, TG_SMEM);
        cudaFuncSetAttribute(k_tgemm64, cudaFuncAttributeMaxDynamicSharedMemorySize, TG64_SMEM);
        smem_set = 1;
    }

    __nv_bfloat16 *w1h, *w1l, *w2h, *w2l, *w3h, *w3l;
    __nv_bfloat16 *wqth, *wqtl, *wkth, *wktl, *wvth, *wvtl, *woth, *wotl;
    __nv_bfloat16 *b1h, *b1l, *b2h, *b2l, *b3h, *b3l, *tokh, *tokl;
    __nv_bfloat16 *clsh, *clsl, *ctxh, *ctxl, *h2h, *h2l;
    float *h3n, *gq, *gk, *gv, *gemb;
    cudaGetSymbolAddress((void**)&w1h, g_w1h);  cudaGetSymbolAddress((void**)&w1l, g_w1l);
    cudaGetSymbolAddress((void**)&w2h, g_w2h);  cudaGetSymbolAddress((void**)&w2l, g_w2l);
    cudaGetSymbolAddress((void**)&w3h, g_w3h);  cudaGetSymbolAddress((void**)&w3l, g_w3l);
    cudaGetSymbolAddress((void**)&wqth, g_wqth); cudaGetSymbolAddress((void**)&wqtl, g_wqtl);
    cudaGetSymbolAddress((void**)&wkth, g_wkth); cudaGetSymbolAddress((void**)&wktl, g_wktl);
    cudaGetSymbolAddress((void**)&wvth, g_wvth); cudaGetSymbolAddress((void**)&wvtl, g_wvtl);
    cudaGetSymbolAddress((void**)&woth, g_woth); cudaGetSymbolAddress((void**)&wotl, g_wotl);
    cudaGetSymbolAddress((void**)&b1h, g_b1h);  cudaGetSymbolAddress((void**)&b1l, g_b1l);
    cudaGetSymbolAddress((void**)&b2h, g_b2h);  cudaGetSymbolAddress((void**)&b2l, g_b2l);
    cudaGetSymbolAddress((void**)&b3h, g_b3h);  cudaGetSymbolAddress((void**)&b3l, g_b3l);
    cudaGetSymbolAddress((void**)&tokh, g_tokh); cudaGetSymbolAddress((void**)&tokl, g_tokl);
    cudaGetSymbolAddress((void**)&clsh, g_clsh); cudaGetSymbolAddress((void**)&clsl, g_clsl);
    cudaGetSymbolAddress((void**)&ctxh, g_ctxh); cudaGetSymbolAddress((void**)&ctxl, g_ctxl);
    cudaGetSymbolAddress((void**)&h2h, g_h2h);  cudaGetSymbolAddress((void**)&h2l, g_h2l);
    cudaGetSymbolAddress((void**)&h3n, g_h3n);
    cudaGetSymbolAddress((void**)&gq, g_q);     cudaGetSymbolAddress((void**)&gemb, g_emb);
    cudaGetSymbolAddress((void**)&gk, g_k);     cudaGetSymbolAddress((void**)&gv, g_v);

    k_setup<<<(NIMG + 127) / 128, 128>>>(pred_boxes, lidar_aug, l2i, img_aug, theta_w, theta_b);
    k_sample<<<dim3((CROP_ * CROP_ + 255) / 256, NIMG), 256>>>(camera_imgs);

    k_cvt_w1<<<(64 * K1P + 255) / 256, 256>>>(conv1);
    k_cvt_w2<<<(256 * 576 + 255) / 256, 256>>>(conv2);
    k_cvt_w3<<<(1024 * 2304 + 255) / 256, 256>>>(conv3);
    k_cvt_wt<<<(1024 * 1024) / 256, 256>>>(wq, wqth, wqtl);
    k_cvt_wt<<<(1024 * 1024) / 256, 256>>>(wk, wkth, wktl);
    k_cvt_wt<<<(1024 * 1024) / 256, 256>>>(wv, wvth, wvtl);
    k_cvt_wt<<<(1024 * 1024) / 256, 256>>>(wo, woth, wotl);

    // conv1 (validated R8 path), h1 emitted as split bf16
    k_im2col1<<<(N1 * 8 + 255) / 256, 256>>>();
    k_tgemm64<<<N1 / 256, 256, TG64_SMEM>>>(w1h, w1l, b1h, b1l, K1P);

    // conv2 -> split h2
    k_im2col2<<<(NIMG * 196 * 72 + 255) / 256, 256>>>();
    k_tgemm<<<dim3(588, 2), 256, TG_SMEM>>>(w2h, w2l, b2h, b2l, 576, 256, nullptr, h2h, h2l, 2);

    // conv3 -> fp32 h3
    k_im2col3<<<(NIMG * 49 * 288 + 255) / 256, 256>>>();
    k_tgemm<<<dim3(147, 8), 256, TG_SMEM>>>(w3h, w3l, b3h, b3l, 2304, 1024, h3n, nullptr, nullptr, 1);

    k_tokens<<<NIMG, 1024>>>(pos);

    // q projection (CLS only), K/V projections
    k_tgemm<<<dim3(3, 8), 256, TG_SMEM>>>(wqth, wqtl, clsh, clsl, 1024, 1024, gq, nullptr, nullptr, 0);
    k_tgemm<<<dim3(150, 8), 256, TG_SMEM>>>(wkth, wktl, tokh, tokl, 1024, 1024, gk, nullptr, nullptr, 0);
    k_tgemm<<<dim3(150, 8), 256, TG_SMEM>>>(wvth, wvtl, tokh, tokl, 1024, 1024, gv, nullptr, nullptr, 0);

    k_attn<<<NIMG, 256>>>(0);

    // output projection
    k_tgemm<<<dim3(3, 8), 256, TG_SMEM>>>(woth, wotl, ctxh, ctxl, 1024, 1024, gemb, nullptr, nullptr, 0);

    k_fuse<<<NBOX, 1024>>>(bdd, momentum, (float*)d_out);
}

// round 13
// speedup vs baseline: 3.8704x; 1.3021x over previous
#include <cuda_runtime.h>
#include <cuda_bf16.h>
#include <math.h>
#include <stdint.h>

#define NB_   32
#define NC_   6
#define NIMG  384
#define NBOX  64
#define CROP_ 224
#define CPAD  228            // halo-padded crop dim (+1 offset, zeroed border)
#define IMG_H_ 512
#define IMG_W_ 1408
#define N1    (NIMG * 3136)
#define K1P   224            // conv1 K: 7 ky * (8 kx-slots * 4 ch)

// ---------------- scratch (device globals; no allocation) ----------------
__device__ float g_theta[NIMG * 6];
__device__ int   g_valid[NIMG];
// halo-padded channel-last crops, split bf16: [img][y 228][x 228][4]
__device__ __align__(16) __nv_bfloat16 g_cropsh[(size_t)NIMG * CPAD * CPAD * 4];
__device__ __align__(16) __nv_bfloat16 g_cropsl[(size_t)NIMG * CPAD * CPAD * 4];
__device__ __align__(16) __nv_bfloat16 g_h1h[(size_t)N1 * 64], g_h1l[(size_t)N1 * 64];
__device__ __align__(16) __nv_bfloat16 g_h2h[NIMG * 196 * 256], g_h2l[NIMG * 196 * 256];
__device__ __align__(16) float g_h3n[NIMG * 49 * 1024];
__device__ __align__(16) float g_k[NIMG * 50 * 1024];
__device__ __align__(16) float g_v[NIMG * 50 * 1024];
__device__ __align__(16) float g_q[NIMG * 1024];
__device__ __align__(16) float g_emb[NIMG * 1024];

__device__ __align__(16) __nv_bfloat16 g_w1h[64 * K1P],    g_w1l[64 * K1P];
__device__ __align__(16) __nv_bfloat16 g_w2h[256 * 576],   g_w2l[256 * 576];
__device__ __align__(16) __nv_bfloat16 g_w3h[1024 * 2304], g_w3l[1024 * 2304];
__device__ __align__(16) __nv_bfloat16 g_wqth[1024 * 1024], g_wqtl[1024 * 1024];
__device__ __align__(16) __nv_bfloat16 g_wkth[1024 * 1024], g_wktl[1024 * 1024];
__device__ __align__(16) __nv_bfloat16 g_wvth[1024 * 1024], g_wvtl[1024 * 1024];
__device__ __align__(16) __nv_bfloat16 g_woth[1024 * 1024], g_wotl[1024 * 1024];
__device__ __align__(16) __nv_bfloat16 g_b2h[NIMG * 196 * 576],  g_b2l[NIMG * 196 * 576];
__device__ __align__(16) __nv_bfloat16 g_b3h[NIMG * 49 * 2304],  g_b3l[NIMG * 49 * 2304];
__device__ __align__(16) __nv_bfloat16 g_tokh[NIMG * 50 * 1024], g_tokl[NIMG * 50 * 1024];
__device__ __align__(16) __nv_bfloat16 g_clsh[NIMG * 1024], g_clsl[NIMG * 1024];
__device__ __align__(16) __nv_bfloat16 g_ctxh[NIMG * 1024], g_ctxl[NIMG * 1024];

// ---------------- PTX helpers (sm_80-portable) ----------------
__device__ __forceinline__ uint32_t smem_u32(const void* p) {
    uint32_t a;
    asm("{ .reg .u64 t; cvta.to.shared.u64 t, %1; cvt.u32.u64 %0, t; }" : "=r"(a) : "l"(p));
    return a;
}
__device__ __forceinline__ void cp16(uint32_t saddr, const void* gptr) {
    asm volatile("cp.async.cg.shared.global [%0], [%1], 16;" :: "r"(saddr), "l"(gptr));
}
#define CP_COMMIT() asm volatile("cp.async.commit_group;" ::: "memory")
#define CP_WAIT1()  asm volatile("cp.async.wait_group 1;" ::: "memory")
#define CP_WAIT0()  asm volatile("cp.async.wait_group 0;" ::: "memory")

__device__ __forceinline__ void ldsm4(uint32_t (&r)[4], uint32_t addr) {
    asm volatile("ldmatrix.sync.aligned.m8n8.x4.shared.b16 {%0,%1,%2,%3}, [%4];"
                 : "=r"(r[0]), "=r"(r[1]), "=r"(r[2]), "=r"(r[3]) : "r"(addr));
}
__device__ __forceinline__ void mma16816(float (&d)[4], const uint32_t (&a)[4],
                                         const uint32_t b0, const uint32_t b1) {
    asm volatile(
        "mma.sync.aligned.m16n8k16.row.col.f32.bf16.bf16.f32 "
        "{%0,%1,%2,%3},{%4,%5,%6,%7},{%8,%9},{%0,%1,%2,%3};"
        : "+f"(d[0]), "+f"(d[1]), "+f"(d[2]), "+f"(d[3])
        : "r"(a[0]), "r"(a[1]), "r"(a[2]), "r"(a[3]), "r"(b0), "r"(b1));
}
__device__ __forceinline__ void split_bf16(float x, __nv_bfloat16* h, __nv_bfloat16* l) {
    __nv_bfloat16 hi = __float2bfloat16(x);
    *h = hi;
    *l = __float2bfloat16(x - __bfloat162float(hi));
}

// common mma compute step on one stage
#define MMA_STAGE(st, AL_OFF, BH_OFF, BL_OFF)                                   \
    {                                                                           \
        const uint32_t aoff = (m0w + (lane & 15)) * 80 + ((lane >> 4) & 1) * 16;\
        const uint32_t boff = (n0w + (lane & 7) + ((lane & 16) >> 1)) * 80 + ((lane & 8) << 1); \
        _Pragma("unroll")                                                       \
        for (int k16 = 0; k16 < 2; k16++) {                                     \
            const uint32_t kb = k16 * 32;                                       \
            uint32_t ah[2][4], al[2][4];                                        \
            ldsm4(ah[0], (st) +            aoff + kb);                          \
            ldsm4(ah[1], (st) +            aoff + 16 * 80 + kb);                \
            ldsm4(al[0], (st) + (AL_OFF) + aoff + kb);                          \
            ldsm4(al[1], (st) + (AL_OFF) + aoff + 16 * 80 + kb);                \
            uint32_t bh[4][4], bl[4][4];                                        \
            _Pragma("unroll")                                                   \
            for (int njp = 0; njp < 4; njp++) {                                 \
                ldsm4(bh[njp], (st) + (BH_OFF) + boff + njp * 16 * 80 + kb);    \
                ldsm4(bl[njp], (st) + (BL_OFF) + boff + njp * 16 * 80 + kb);    \
            }                                                                   \
            _Pragma("unroll")                                                   \
            for (int mi = 0; mi < 2; mi++)                                      \
                _Pragma("unroll")                                               \
                for (int njp = 0; njp < 4; njp++) {                             \
                    mma16816(acc[mi][2 * njp],     ah[mi], bh[njp][0], bh[njp][1]); \
                    mma16816(acc[mi][2 * njp + 1], ah[mi], bh[njp][2], bh[njp][3]); \
                    mma16816(acc[mi][2 * njp],     ah[mi], bl[njp][0], bl[njp][1]); \
                    mma16816(acc[mi][2 * njp + 1], ah[mi], bl[njp][2], bl[njp][3]); \
                    mma16816(acc[mi][2 * njp],     al[mi], bh[njp][0], bh[njp][1]); \
                    mma16816(acc[mi][2 * njp + 1], al[mi], bh[njp][2], bh[njp][3]); \
                }                                                               \
        }                                                                       \
    }

// =============== generic split-bf16 GEMM (128x128 tile) ===============
// mode 0: fp32 out; 1: fp32+relu; 2: relu + split-bf16 out (outh/outl)
#define STG_BYTES 40960
__global__ __launch_bounds__(256, 1) void k_tgemm(
    const __nv_bfloat16* __restrict__ Ahi, const __nv_bfloat16* __restrict__ Alo,
    const __nv_bfloat16* __restrict__ Bhi, const __nv_bfloat16* __restrict__ Blo,
    int K, int OC, float* __restrict__ out,
    __nv_bfloat16* __restrict__ outh, __nv_bfloat16* __restrict__ outl, int mode) {
    extern __shared__ __align__(128) char smem[];
    const uint32_t sbase = smem_u32(smem);
    const int tid = threadIdx.x;
    const int wid = tid >> 5, lane = tid & 31;
    const int m0 = blockIdx.y * 128, n0 = blockIdx.x * 128;
    const int wm = wid & 3, wn = wid >> 2;
    const int m0w = wm * 32, n0w = wn * 64;

    float acc[2][8][4] = {};
    const int lrow = tid >> 2;
    const int lc = (tid & 3) * 16;

#define TG_LOAD(BUF, KC0) {                                                     \
        uint32_t sb = sbase + (BUF) * STG_BYTES;                                \
        _Pragma("unroll")                                                       \
        for (int h = 0; h < 2; h++) {                                           \
            int row = lrow + h * 64;                                            \
            uint32_t so = row * 80 + lc;                                        \
            size_t ga = (size_t)(m0 + row) * K + (KC0) + (lc >> 1);             \
            size_t gb = (size_t)(n0 + row) * K + (KC0) + (lc >> 1);             \
            cp16(sb + so,         Ahi + ga);                                    \
            cp16(sb + 10240 + so, Alo + ga);                                    \
            cp16(sb + 20480 + so, Bhi + gb);                                    \
            cp16(sb + 30720 + so, Blo + gb);                                    \
        }                                                                       \
        CP_COMMIT();                                                            \
    }

    const int nch = K >> 5;
    TG_LOAD(0, 0);
#pragma unroll 1
    for (int ch = 0; ch < nch; ch++) {
        if (ch + 1 < nch) { TG_LOAD((ch + 1) & 1, (ch + 1) * 32); CP_WAIT1(); }
        else              { CP_WAIT0(); }
        __syncthreads();
        const uint32_t st = sbase + (ch & 1) * STG_BYTES;
        MMA_STAGE(st, 10240, 20480, 30720);
        __syncthreads();
    }
#undef TG_LOAD

    const int rbase = m0 + m0w + (lane >> 2);
    const int cbase = n0 + n0w + ((lane & 3) << 1);
#pragma unroll
    for (int mi = 0; mi < 2; mi++)
#pragma unroll
        for (int nj = 0; nj < 8; nj++) {
            float* d = acc[mi][nj];
            int row = rbase + mi * 16;
            int col = cbase + nj * 8;
#pragma unroll
            for (int e = 0; e < 4; e++) {
                int r = row + (e >> 1) * 8;
                int c = col + (e & 1);
                float v = d[e];
                if (mode >= 1) v = fmaxf(v, 0.f);
                size_t o = (size_t)c * OC + r;
                if (mode == 2) split_bf16(v, outh + o, outl + o);
                else out[o] = v;
            }
        }
}

// =============== conv1: 64x256 tile, fused im2col-B from halo crops ===============
// (validated by R9/R11 bit-identical rel_err forensics)
#define STG64 51200
__global__ __launch_bounds__(256) void k_tgemm_c1() {
    extern __shared__ __align__(128) char smem[];
    const uint32_t sbase = smem_u32(smem);
    const int tid = threadIdx.x;
    const int wid = tid >> 5, lane = tid & 31;
    const int n0 = blockIdx.x * 256;
    const int wm = wid & 1, wn = wid >> 1;     // 2 x 4 warp grid
    const int m0w = wm * 32, n0w = wn * 64;

    float acc[2][8][4] = {};

    // per-thread B row (output pixel) base pointer into halo crops
    const int n = n0 + tid;
    const int img = n / 3136, px = n - img * 3136;
    const int oy = px / 56, ox = px - oy * 56;
    const __nv_bfloat16* bsh = g_cropsh + ((size_t)(img * CPAD + oy * 4) * CPAD + ox * 4) * 4;
    const __nv_bfloat16* bsl = g_cropsl + ((size_t)(img * CPAD + oy * 4) * CPAD + ox * 4) * 4;

#define C1_LOAD(BUF, KY) {                                                      \
        uint32_t sb = sbase + (BUF) * STG64;                                    \
        if (tid < 128) {                                                        \
            int row = tid >> 1, half = tid & 1;                                 \
            uint32_t so = row * 80 + half * 32;                                 \
            size_t ga = (size_t)row * K1P + (KY) * 32 + half * 16;              \
            cp16(sb + so,        g_w1h + ga);                                   \
            cp16(sb + so + 16,   g_w1h + ga + 8);                               \
            cp16(sb + 5120 + so,      g_w1l + ga);                              \
            cp16(sb + 5120 + so + 16, g_w1l + ga + 8);                          \
        }                                                                       \
        {                                                                       \
            uint32_t so = sb + 10240 + tid * 80;                                \
            const __nv_bfloat16* ph = bsh + (size_t)(KY) * (CPAD * 4);          \
            cp16(so, ph); cp16(so + 16, ph + 8);                                \
            cp16(so + 32, ph + 16); cp16(so + 48, ph + 24);                     \
            so += 20480;                                                        \
            const __nv_bfloat16* pl = bsl + (size_t)(KY) * (CPAD * 4);          \
            cp16(so, pl); cp16(so + 16, pl + 8);                                \
            cp16(so + 32, pl + 16); cp16(so + 48, pl + 24);                     \
        }                                                                       \
        CP_COMMIT();                                                            \
    }

    C1_LOAD(0, 0);
#pragma unroll 1
    for (int ch = 0; ch < 7; ch++) {
        if (ch + 1 < 7) { C1_LOAD((ch + 1) & 1, ch + 1); CP_WAIT1(); }
        else            { CP_WAIT0(); }
        __syncthreads();
        const uint32_t st = sbase + (ch & 1) * STG64;
        MMA_STAGE(st, 5120, 10240, 30720);
        __syncthreads();
    }
#undef C1_LOAD

    const int rbase = m0w + (lane >> 2);
    const int cbase = n0 + n0w + ((lane & 3) << 1);
#pragma unroll
    for (int mi = 0; mi < 2; mi++)
#pragma unroll
        for (int nj = 0; nj < 8; nj++) {
            float* d = acc[mi][nj];
            int row = rbase + mi * 16;
            int col = cbase + nj * 8;
#pragma unroll
            for (int e = 0; e < 4; e++) {
                int r = row + (e >> 1) * 8;
                int c = col + (e & 1);
                float v = fmaxf(d[e], 0.f);
                size_t o = (size_t)c * 64 + r;
                split_bf16(v, g_h1h + o, g_h1l + o);
            }
        }
}

// ---------------- weight conversions ----------------
// conv1 W[64][3][7][7] -> [oc][ky*32 + kx*4 + ch], kx slot 7 & ch 3 zero
__global__ void k_cvt_w1(const float* __restrict__ W) {
    int i = blockIdx.x * blockDim.x + threadIdx.x;
    if (i >= 64 * K1P) return;
    int oc = i / K1P, kp = i - oc * K1P;
    int ky = kp >> 5, rem = kp & 31;
    int kx = rem >> 2, ch = rem & 3;
    float v = (kx < 7 && ch < 3) ? W[oc * 147 + ch * 49 + ky * 7 + kx] : 0.f;
    split_bf16(v, g_w1h + i, g_w1l + i);
}
__global__ void k_cvt_w2(const float* __restrict__ W) {
    int i = blockIdx.x * blockDim.x + threadIdx.x;
    if (i >= 256 * 576) return;
    int oc = i / 576, kp = i - oc * 576;
    int r = kp >> 6, ic = kp & 63;
    split_bf16(W[oc * 576 + ic * 9 + r], g_w2h + i, g_w2l + i);
}
__global__ void k_cvt_w3(const float* __restrict__ W) {
    int i = blockIdx.x * blockDim.x + threadIdx.x;
    if (i >= 1024 * 2304) return;
    int oc = i / 2304, kp = i - oc * 2304;
    int r = kp >> 8, ic = kp & 255;
    split_bf16(W[(size_t)oc * 2304 + ic * 9 + r], g_w3h + i, g_w3l + i);
}
__global__ void k_cvt_wt(const float* __restrict__ W,
                         __nv_bfloat16* __restrict__ hi,
                         __nv_bfloat16* __restrict__ lo) {
    int i = blockIdx.x * blockDim.x + threadIdx.x;
    int n = i >> 10, k = i & 1023;
    split_bf16(W[k * 1024 + n], hi + i, lo + i);
}

// ---------------- im2col copy kernels (uint4 = 8 bf16, stride q*8) ----------------
__global__ void k_im2col2() {
    int i = blockIdx.x * blockDim.x + threadIdx.x;   // n2*72 + r*8 + q
    if (i >= NIMG * 196 * 72) return;
    int n2 = i / 72, rem = i - n2 * 72;
    int r = rem >> 3, q8 = (rem & 7) * 8;
    int img = n2 / 196, px = n2 - img * 196;
    int oy = px / 14, ox = px - oy * 14;
    int iy = oy * 4 + r / 3, ix = ox * 4 + (r % 3);
    size_t src = ((size_t)(img * 3136 + iy * 56 + ix)) * 64 + q8;
    size_t dst = (size_t)n2 * 576 + r * 64 + q8;
    *(uint4*)(g_b2h + dst) = *(const uint4*)(g_h1h + src);
    *(uint4*)(g_b2l + dst) = *(const uint4*)(g_h1l + src);
}
__global__ void k_im2col3() {
    int i = blockIdx.x * blockDim.x + threadIdx.x;   // n3*288 + r*32 + q
    if (i >= NIMG * 49 * 288) return;
    int n3 = i / 288, rem = i - n3 * 288;
    int r = rem >> 5, q8 = (rem & 31) * 8;
    int img = n3 / 49, px = n3 - img * 49;
    int oy = px / 7, ox = px - oy * 7;
    int iy = oy * 2 + r / 3, ix = ox * 2 + (r % 3);
    size_t dst = (size_t)n3 * 2304 + r * 256 + q8;
    if (iy < 14 && ix < 14) {
        size_t src = ((size_t)(img * 196 + iy * 14 + ix)) * 256 + q8;
        *(uint4*)(g_b3h + dst) = *(const uint4*)(g_h2h + src);
        *(uint4*)(g_b3l + dst) = *(const uint4*)(g_h2l + src);
    } else {
        uint4 z = {0u, 0u, 0u, 0u};
        *(uint4*)(g_b3h + dst) = z;
        *(uint4*)(g_b3l + dst) = z;
    }
}

// ---------------- crop halo zero (rows/cols 0,225,226,227) ----------------
__global__ void k_zero_crop_halo() {
    int i = blockIdx.x * blockDim.x + threadIdx.x;   // img*1824 + r
    if (i >= NIMG * 1824) return;
    int img = i / 1824, r = i - img * 1824;
    int y, x;
    if (r < 912) { int qq = r / 228; y = (qq == 0) ? 0 : 224 + qq; x = r % 228; }
    else { int r2 = r - 912; int qq = r2 / 228; x = (qq == 0) ? 0 : 224 + qq; y = r2 % 228; }
    size_t o = ((size_t)(img * CPAD + y) * CPAD + x) * 4;
    uint2 z = {0u, 0u};
    *(uint2*)(g_cropsh + o) = z;
    *(uint2*)(g_cropsl + o) = z;
}

// ---------------- stage 0: projection + affine theta ----------------
__global__ void k_setup(const float* __restrict__ pred_boxes,
                        const float* __restrict__ la_m,
                        const float* __restrict__ l2i_m,
                        const float* __restrict__ aug_m,
                        const float* __restrict__ theta_w,
                        const float* __restrict__ theta_b) {
    int t = blockIdx.x * blockDim.x + threadIdx.x;
    if (t >= NIMG) return;
    int n = t / NC_, c = t % NC_;
    int b = n / NB_, nb = n % NB_;
    const float* pb = pred_boxes + (b * NB_ + nb) * 9;

    float r[4];
#pragma unroll
    for (int i = 0; i < 4; i++) {
        float s = theta_b[i];
#pragma unroll
        for (int j = 0; j < 9; j++) s += theta_w[i * 9 + j] * pb[j];
        r[i] = tanhf(s);
    }

    const float* la = la_m + b * 16;
    float px0 = pb[0] - la[3], py0 = pb[1] - la[7], pz0 = pb[2] - la[11];
    float a00 = la[0], a01 = la[1], a02 = la[2];
    float a10 = la[4], a11 = la[5], a12 = la[6];
    float a20 = la[8], a21 = la[9], a22 = la[10];
    float det = a00 * (a11 * a22 - a12 * a21) - a01 * (a10 * a22 - a12 * a20)
              + a02 * (a10 * a21 - a11 * a20);
    float id = 1.f / det;
    float i00 = (a11 * a22 - a12 * a21) * id, i01 = (a02 * a21 - a01 * a22) * id, i02 = (a01 * a12 - a02 * a11) * id;
    float i10 = (a12 * a20 - a10 * a22) * id, i11 = (a00 * a22 - a02 * a20) * id, i12 = (a02 * a10 - a00 * a12) * id;
    float i20 = (a10 * a21 - a11 * a20) * id, i21 = (a01 * a20 - a00 * a21) * id, i22 = (a00 * a11 - a01 * a10) * id;
    float px = i00 * px0 + i01 * py0 + i02 * pz0;
    float py = i10 * px0 + i11 * py0 + i12 * pz0;
    float pz = i20 * px0 + i21 * py0 + i22 * pz0;

    const float* m = l2i_m + (b * NC_ + c) * 16;
    float qx = m[0] * px + m[1] * py + m[2] * pz + m[3];
    float qy = m[4] * px + m[5] * py + m[6] * pz + m[7];
    float qz = m[8] * px + m[9] * py + m[10] * pz + m[11];
    float z = fminf(fmaxf(qz, 1e-5f), 100000.f);
    float x = qx / z, y = qy / z;
    const float* g = aug_m + (b * NC_ + c) * 16;
    float u = g[0] * x + g[1] * y + g[2] * z + g[3];
    float v = g[4] * x + g[5] * y + g[6] * z + g[7];
    int on = (v < (float)IMG_H_) && (v >= 0.f) && (u < (float)IMG_W_) && (u >= 0.f);
    float ty = v / (float)IMG_H_ * 2.f - 1.f;
    float tx = u / (float)IMG_W_ * 2.f - 1.f;

    int idx = n * NC_ + c;
    g_theta[idx * 6 + 0] = r[0]; g_theta[idx * 6 + 1] = r[1]; g_theta[idx * 6 + 2] = tx;
    g_theta[idx * 6 + 3] = r[2]; g_theta[idx * 6 + 4] = r[3]; g_theta[idx * 6 + 5] = ty;
    g_valid[idx] = on;
}

// ---------------- stage 1: grid sample -> halo-padded split crops ----------------
__global__ void k_sample(const float* __restrict__ imgs) {
    int img = blockIdx.y;
    int p = blockIdx.x * blockDim.x + threadIdx.x;
    if (p >= CROP_ * CROP_) return;
    int oy = p / CROP_, ox = p - oy * CROP_;
    const float* th = g_theta + img * 6;
    float gx = (2.f * ox + 1.f) / CROP_ - 1.f;
    float gy = (2.f * oy + 1.f) / CROP_ - 1.f;
    float grx = th[0] * gx + th[1] * gy + th[2];
    float gry = th[3] * gx + th[4] * gy + th[5];
    float ix = ((grx + 1.f) * IMG_W_ - 1.f) * 0.5f;
    float iy = ((gry + 1.f) * IMG_H_ - 1.f) * 0.5f;
    float x0 = floorf(ix), y0 = floorf(iy);
    float wx = ix - x0, wy = iy - y0;
    float x1 = x0 + 1.f, y1 = y0 + 1.f;

    int n = img / NC_, c = img - n * NC_, b = n / NB_;
    const float* base = imgs + (size_t)(b * NC_ + c) * 3 * IMG_H_ * IMG_W_;

    int xi0 = (int)fminf(fmaxf(x0, 0.f), (float)(IMG_W_ - 1));
    int xi1 = (int)fminf(fmaxf(x1, 0.f), (float)(IMG_W_ - 1));
    int yi0 = (int)fminf(fmaxf(y0, 0.f), (float)(IMG_H_ - 1));
    int yi1 = (int)fminf(fmaxf(y1, 0.f), (float)(IMG_H_ - 1));
    float vx0 = (x0 >= 0.f && x0 <= (float)(IMG_W_ - 1)) ? 1.f : 0.f;
    float vx1 = (x1 >= 0.f && x1 <= (float)(IMG_W_ - 1)) ? 1.f : 0.f;
    float vy0 = (y0 >= 0.f && y0 <= (float)(IMG_H_ - 1)) ? 1.f : 0.f;
    float vy1 = (y1 >= 0.f && y1 <= (float)(IMG_H_ - 1)) ? 1.f : 0.f;
    float w00 = (1.f - wx) * (1.f - wy) * vx0 * vy0;
    float w01 = wx * (1.f - wy) * vx1 * vy0;
    float w10 = (1.f - wx) * wy * vx0 * vy1;
    float w11 = wx * wy * vx1 * vy1;

    union { __nv_bfloat16 b16[4]; uint2 u; } uh, ul;
#pragma unroll
    for (int ch = 0; ch < 3; ch++) {
        const float* ib = base + (size_t)ch * IMG_H_ * IMG_W_;
        float v00 = ib[yi0 * IMG_W_ + xi0];
        float v01 = ib[yi0 * IMG_W_ + xi1];
        float v10 = ib[yi1 * IMG_W_ + xi0];
        float v11 = ib[yi1 * IMG_W_ + xi1];
        float v = v00 * w00 + v01 * w01 + v10 * w10 + v11 * w11;
        split_bf16(v, &uh.b16[ch], &ul.b16[ch]);
    }
    uh.b16[3] = __float2bfloat16(0.f);
    ul.b16[3] = __float2bfloat16(0.f);
    size_t o = ((size_t)(img * CPAD + oy + 1) * CPAD + (ox + 1)) * 4;
    *(uint2*)(g_cropsh + o) = uh.u;
    *(uint2*)(g_cropsl + o) = ul.u;
}

// ---------------- tokens: split tok + contiguous cls split ----------------
__global__ void k_tokens(const float* __restrict__ pos) {
    int img = blockIdx.x;
    int d = threadIdx.x;    // 1024
    float s = 0.f;
    __nv_bfloat16* th = g_tokh + (size_t)img * 50 * 1024;
    __nv_bfloat16* tl = g_tokl + (size_t)img * 50 * 1024;
#pragma unroll 7
    for (int t = 0; t < 49; t++) {
        float v = g_h3n[((size_t)img * 49 + t) * 1024 + d];
        s += v;
        float tv = v + pos[(t + 1) * 1024 + d];
        split_bf16(tv, th + (t + 1) * 1024 + d, tl + (t + 1) * 1024 + d);
    }
    float cls = s * (1.f / 49.f) + pos[d];
    __nv_bfloat16 ch_, cl_;
    split_bf16(cls, &ch_, &cl_);
    th[d] = ch_; tl[d] = cl_;
    g_clsh[(size_t)img * 1024 + d] = ch_;
    g_clsl[(size_t)img * 1024 + d] = cl_;
}

// ---------------- attention core: scores + softmax + ctx (split out) ----------------
__global__ void k_attn(int dummy) {
    __shared__ float qs[1024];
    __shared__ float sc[50];
    __shared__ float pr[50];
    int img = blockIdx.x, tid = threadIdx.x;   // 256
    for (int i = tid; i < 1024; i += 256) qs[i] = g_q[(size_t)img * 1024 + i];
    __syncthreads();

    int wid = tid >> 5, lid = tid & 31;
    for (int t = wid; t < 50; t += 8) {
        const float* kr = g_k + ((size_t)img * 50 + t) * 1024;
        float s = 0.f;
        for (int d = lid; d < 1024; d += 32) s = fmaf(qs[d], kr[d], s);
#pragma unroll
        for (int o = 16; o > 0; o >>= 1) s += __shfl_xor_sync(0xffffffffu, s, o);
        if (lid == 0) sc[t] = s * 0.03125f;
    }
    __syncthreads();
    if (tid == 0) {
        float mx = -1e30f;
        for (int t = 0; t < 50; t++) mx = fmaxf(mx, sc[t]);
        float sum = 0.f;
        for (int t = 0; t < 50; t++) { float e = expf(sc[t] - mx); pr[t] = e; sum += e; }
        float inv = 1.f / sum;
        for (int t = 0; t < 50; t++) pr[t] *= inv;
    }
    __syncthreads();
    {
        float4 acc = {0.f, 0.f, 0.f, 0.f};
        const float4* v4 = (const float4*)(g_v + (size_t)img * 50 * 1024);
        for (int t = 0; t < 50; t++) {
            float p = pr[t];
            float4 v = v4[t * 256 + tid];
            acc.x = fmaf(p, v.x, acc.x); acc.y = fmaf(p, v.y, acc.y);
            acc.z = fmaf(p, v.z, acc.z); acc.w = fmaf(p, v.w, acc.w);
        }
        size_t o = (size_t)img * 1024 + tid * 4;
        split_bf16(acc.x, g_ctxh + o + 0, g_ctxl + o + 0);
        split_bf16(acc.y, g_ctxh + o + 1, g_ctxl + o + 1);
        split_bf16(acc.z, g_ctxh + o + 2, g_ctxl + o + 2);
        split_bf16(acc.w, g_ctxh + o + 3, g_ctxl + o + 3);
    }
}

// ---------------- momentum fusion ----------------
__global__ void k_fuse(const float* __restrict__ bdd,
                       const float* __restrict__ mom_p,
                       float* __restrict__ out) {
    int n = blockIdx.x, d = threadIdx.x;
    float mom = *mom_p;
    float e = bdd[d];
    const int order[6] = {2, 0, 1, 5, 3, 4};
#pragma unroll
    for (int i = 0; i < 6; i++) {
        int c = order[i];
        if (g_valid[n * 6 + c])
            e = mom * e + (1.f - mom) * g_emb[((size_t)(n * 6 + c)) * 1024 + d];
    }
    out[(size_t)n * 1024 + d] = e;
}

// ---------------- launch ----------------
extern "C" void kernel_launch(void* const* d_in, const int* in_sizes, int n_in,
                              void* d_out, int out_size) {
    const float* camera_imgs = (const float*)d_in[0];
    const float* pred_boxes  = (const float*)d_in[1];
    const float* img_aug     = (const float*)d_in[2];
    const float* lidar_aug   = (const float*)d_in[3];
    const float* l2i         = (const float*)d_in[4];
    const float* momentum    = (const float*)d_in[5];
    const float* bdd         = (const float*)d_in[6];
    const float* theta_w     = (const float*)d_in[7];
    const float* theta_b     = (const float*)d_in[8];
    const float* conv1       = (const float*)d_in[9];
    const float* conv2       = (const float*)d_in[10];
    const float* conv3       = (const float*)d_in[11];
    const float* pos         = (const float*)d_in[12];
    const float* wq          = (const float*)d_in[13];
    const float* wk          = (const float*)d_in[14];
    const float* wv          = (const float*)d_in[15];
    const float* wo          = (const float*)d_in[16];

    const int TG_SMEM = 2 * STG_BYTES;   // 81920
    const int C1_SMEM = 2 * STG64;       // 102400
    static int smem_set = 0;
    if (!smem_set) {
        cudaFuncSetAttribute(k_tgemm, cudaFuncAttributeMaxDynamicSharedMemorySize, TG_SMEM);
        cudaFuncSetAttribute(k_tgemm_c1, cudaFuncAttributeMaxDynamicSharedMemorySize, C1_SMEM);
        smem_set = 1;
    }

    __nv_bfloat16 *w2h, *w2l, *w3h, *w3l;
    __nv_bfloat16 *wqth, *wqtl, *wkth, *wktl, *wvth, *wvtl, *woth, *wotl;
    __nv_bfloat16 *b2h, *b2l, *b3h, *b3l, *tokh, *tokl;
    __nv_bfloat16 *clsh, *clsl, *ctxh, *ctxl, *h2h, *h2l;
    float *h3n, *gq, *gk, *gv, *gemb;
    cudaGetSymbolAddress((void**)&w2h, g_w2h);  cudaGetSymbolAddress((void**)&w2l, g_w2l);
    cudaGetSymbolAddress((void**)&w3h, g_w3h);  cudaGetSymbolAddress((void**)&w3l, g_w3l);
    cudaGetSymbolAddress((void**)&wqth, g_wqth); cudaGetSymbolAddress((void**)&wqtl, g_wqtl);
    cudaGetSymbolAddress((void**)&wkth, g_wkth); cudaGetSymbolAddress((void**)&wktl, g_wktl);
    cudaGetSymbolAddress((void**)&wvth, g_wvth); cudaGetSymbolAddress((void**)&wvtl, g_wvtl);
    cudaGetSymbolAddress((void**)&woth, g_woth); cudaGetSymbolAddress((void**)&wotl, g_wotl);
    cudaGetSymbolAddress((void**)&b2h, g_b2h);  cudaGetSymbolAddress((void**)&b2l, g_b2l);
    cudaGetSymbolAddress((void**)&b3h, g_b3h);  cudaGetSymbolAddress((void**)&b3l, g_b3l);
    cudaGetSymbolAddress((void**)&tokh, g_tokh); cudaGetSymbolAddress((void**)&tokl, g_tokl);
    cudaGetSymbolAddress((void**)&clsh, g_clsh); cudaGetSymbolAddress((void**)&clsl, g_clsl);
    cudaGetSymbolAddress((void**)&ctxh, g_ctxh); cudaGetSymbolAddress((void**)&ctxl, g_ctxl);
    cudaGetSymbolAddress((void**)&h2h, g_h2h);  cudaGetSymbolAddress((void**)&h2l, g_h2l);
    cudaGetSymbolAddress((void**)&h3n, g_h3n);
    cudaGetSymbolAddress((void**)&gq, g_q);     cudaGetSymbolAddress((void**)&gemb, g_emb);
    cudaGetSymbolAddress((void**)&gk, g_k);     cudaGetSymbolAddress((void**)&gv, g_v);

    k_setup<<<(NIMG + 127) / 128, 128>>>(pred_boxes, lidar_aug, l2i, img_aug, theta_w, theta_b);
    k_zero_crop_halo<<<(NIMG * 1824 + 255) / 256, 256>>>();
    k_sample<<<dim3((CROP_ * CROP_ + 255) / 256, NIMG), 256>>>(camera_imgs);

    k_cvt_w1<<<(64 * K1P + 255) / 256, 256>>>(conv1);
    k_cvt_w2<<<(256 * 576 + 255) / 256, 256>>>(conv2);
    k_cvt_w3<<<(1024 * 2304 + 255) / 256, 256>>>(conv3);
    k_cvt_wt<<<(1024 * 1024) / 256, 256>>>(wq, wqth, wqtl);
    k_cvt_wt<<<(1024 * 1024) / 256, 256>>>(wk, wkth, wktl);
    k_cvt_wt<<<(1024 * 1024) / 256, 256>>>(wv, wvth, wvtl);
    k_cvt_wt<<<(1024 * 1024) / 256, 256>>>(wo, woth, wotl);

    // conv1: fused im2col GEMM (no b1 buffer) -> h1 split
    k_tgemm_c1<<<N1 / 256, 256, C1_SMEM>>>();

    // conv2 -> split h2
    k_im2col2<<<(NIMG * 196 * 72 + 255) / 256, 256>>>();
    k_tgemm<<<dim3(588, 2), 256, TG_SMEM>>>(w2h, w2l, b2h, b2l, 576, 256, nullptr, h2h, h2l, 2);

    // conv3 -> fp32 h3
    k_im2col3<<<(NIMG * 49 * 288 + 255) / 256, 256>>>();
    k_tgemm<<<dim3(147, 8), 256, TG_SMEM>>>(w3h, w3l, b3h, b3l, 2304, 1024, h3n, nullptr, nullptr, 1);

    k_tokens<<<NIMG, 1024>>>(pos);

    // q projection (CLS only), K/V projections
    k_tgemm<<<dim3(3, 8), 256, TG_SMEM>>>(wqth, wqtl, clsh, clsl, 1024, 1024, gq, nullptr, nullptr, 0);
    k_tgemm<<<dim3(150, 8), 256, TG_SMEM>>>(wkth, wktl, tokh, tokl, 1024, 1024, gk, nullptr, nullptr, 0);
    k_tgemm<<<dim3(150, 8), 256, TG_SMEM>>>(wvth, wvtl, tokh, tokl, 1024, 1024, gv, nullptr, nullptr, 0);

    k_attn<<<NIMG, 256>>>(0);

    // output projection
    k_tgemm<<<dim3(3, 8), 256, TG_SMEM>>>(woth, wotl, ctxh, ctxl, 1024, 1024, gemb, nullptr, nullptr, 0);

    k_fuse<<<NBOX, 1024>>>(bdd, momentum, (float*)d_out);
}